// round 1
// baseline (speedup 1.0000x reference)
#include <cuda_runtime.h>
#include <math.h>
#include <cstdint>

// Problem dims
constexpr int NB  = 8;      // bags
constexpr int NI  = 2048;   // instances per bag
constexpr int DIM = 1024;   // input embed
constexpr int HD  = 512;    // hidden
constexpr int DA  = 256;    // attention dim
constexpr int KN  = 5;      // neighbors
constexpr int NC  = 2;      // classes

// Scratch (device globals; no dynamic allocation allowed)
__device__ float d_x [NB * NI * HD];          // 32 MB  : relu(h@W_fc+b)
__device__ float d_sq[NB * NI];
__device__ float d_d2[(size_t)NB * NI * NI];  // 128 MB : pairwise sq dist
__device__ int   d_idx[NB * NI * KN];
__device__ float d_P [NB * NI * HD];          // x @ Wg_top
__device__ float d_Q [NB * NI * HD];          // x @ Wg_bot
__device__ float d_g [NB * NI * HD];          // edgeconv output
__device__ float d_Ap[NB * NI * DA];          // g @ W_a
__device__ float d_Bp[NB * NI * DA];          // g @ W_b
__device__ float d_Ar[NB * NI];               // A_raw
__device__ float d_M [NB * HD];               // pooled

// ---------------------------------------------------------------------------
// Generic tiled fp32 GEMM: C[M,Nd] = act(A[M,Kd] @ B[Kd,Nd] + bias)
// Requires M%64==0, Nd%64==0, Kd%16==0 (true for all calls here).
// ---------------------------------------------------------------------------
template <int ACT>
__global__ void gemm_bias_kernel(const float* __restrict__ A,
                                 const float* __restrict__ Bm,
                                 const float* __restrict__ bias,
                                 float* __restrict__ Cm,
                                 int M, int Kd, int Nd) {
    constexpr int BM = 64, BN = 64, BK = 16, TM = 4, TN = 4;
    __shared__ float As[BK][BM];
    __shared__ float Bs[BK][BN];
    const int tid = threadIdx.x;
    const int tx = tid & 15, ty = tid >> 4;
    const int rowBase = blockIdx.y * BM;
    const int colBase = blockIdx.x * BN;

    float acc[TM][TN];
#pragma unroll
    for (int m = 0; m < TM; m++)
#pragma unroll
        for (int n = 0; n < TN; n++) acc[m][n] = 0.f;

    for (int k0 = 0; k0 < Kd; k0 += BK) {
#pragma unroll
        for (int i = tid; i < BM * BK; i += 256) {
            int r = i >> 4, c = i & 15;
            As[c][r] = A[(size_t)(rowBase + r) * Kd + k0 + c];
        }
#pragma unroll
        for (int i = tid; i < BK * BN; i += 256) {
            int r = i >> 6, c = i & 63;
            Bs[r][c] = Bm[(size_t)(k0 + r) * Nd + colBase + c];
        }
        __syncthreads();
#pragma unroll
        for (int kk = 0; kk < BK; kk++) {
            float av[TM], bv[TN];
#pragma unroll
            for (int m = 0; m < TM; m++) av[m] = As[kk][ty * TM + m];
#pragma unroll
            for (int n = 0; n < TN; n++) bv[n] = Bs[kk][tx * TN + n];
#pragma unroll
            for (int m = 0; m < TM; m++)
#pragma unroll
                for (int n = 0; n < TN; n++)
                    acc[m][n] = fmaf(av[m], bv[n], acc[m][n]);
        }
        __syncthreads();
    }

#pragma unroll
    for (int m = 0; m < TM; m++) {
        int r = rowBase + ty * TM + m;
#pragma unroll
        for (int n = 0; n < TN; n++) {
            int c = colBase + tx * TN + n;
            float v = acc[m][n];
            if (bias) v += bias[c];
            if (ACT == 1) v = fmaxf(v, 0.f);
            Cm[(size_t)r * Nd + c] = v;
        }
    }
}

// ---------------------------------------------------------------------------
// Row squared norms of d_x
// ---------------------------------------------------------------------------
__global__ void sqnorm_kernel() {
    int row = blockIdx.x, tid = threadIdx.x;
    __shared__ float sh[4];
    const float* xr = d_x + (size_t)row * HD;
    float s = 0.f;
    for (int hh = tid; hh < HD; hh += 128) { float v = xr[hh]; s = fmaf(v, v, s); }
    int lane = tid & 31, w = tid >> 5;
#pragma unroll
    for (int o = 16; o > 0; o >>= 1) s += __shfl_down_sync(0xffffffffu, s, o);
    if (lane == 0) sh[w] = s;
    __syncthreads();
    if (tid == 0) d_sq[row] = sh[0] + sh[1] + sh[2] + sh[3];
}

// ---------------------------------------------------------------------------
// Per-bag Gram -> squared distances: d2[i][j] = sq[i]+sq[j]-2*x_i.x_j
// ---------------------------------------------------------------------------
__global__ void gram_d2_kernel() {
    constexpr int BM = 64, BN = 64, BK = 16, TM = 4, TN = 4;
    __shared__ float As[BK][BM];
    __shared__ float Bs[BK][BN];
    const int b = blockIdx.z;
    const float* Xb  = d_x  + (size_t)b * NI * HD;
    const float* sqb = d_sq + (size_t)b * NI;
    float* d2b = d_d2 + (size_t)b * NI * NI;
    const int tid = threadIdx.x;
    const int tx = tid & 15, ty = tid >> 4;
    const int rowBase = blockIdx.y * BM;
    const int colBase = blockIdx.x * BN;

    float acc[TM][TN];
#pragma unroll
    for (int m = 0; m < TM; m++)
#pragma unroll
        for (int n = 0; n < TN; n++) acc[m][n] = 0.f;

    for (int k0 = 0; k0 < HD; k0 += BK) {
#pragma unroll
        for (int i = tid; i < BM * BK; i += 256) {
            int r = i >> 4, c = i & 15;
            As[c][r] = Xb[(size_t)(rowBase + r) * HD + k0 + c];
        }
#pragma unroll
        for (int i = tid; i < BN * BK; i += 256) {
            int r = i >> 4, c = i & 15;
            Bs[c][r] = Xb[(size_t)(colBase + r) * HD + k0 + c];
        }
        __syncthreads();
#pragma unroll
        for (int kk = 0; kk < BK; kk++) {
            float av[TM], bv[TN];
#pragma unroll
            for (int m = 0; m < TM; m++) av[m] = As[kk][ty * TM + m];
#pragma unroll
            for (int n = 0; n < TN; n++) bv[n] = Bs[kk][tx * TN + n];
#pragma unroll
            for (int m = 0; m < TM; m++)
#pragma unroll
                for (int n = 0; n < TN; n++)
                    acc[m][n] = fmaf(av[m], bv[n], acc[m][n]);
        }
        __syncthreads();
    }

#pragma unroll
    for (int m = 0; m < TM; m++) {
        int r = rowBase + ty * TM + m;
#pragma unroll
        for (int n = 0; n < TN; n++) {
            int c = colBase + tx * TN + n;
            d2b[(size_t)r * NI + c] = sqb[r] + sqb[c] - 2.f * acc[m][n];
        }
    }
}

// ---------------------------------------------------------------------------
// Top-K smallest distances per row. One warp per row; tie-break: lower index.
// ---------------------------------------------------------------------------
__global__ void topk_kernel() {
    const int w    = threadIdx.x >> 5;
    const int lane = threadIdx.x & 31;
    const int row  = blockIdx.x * 4 + w;
    const int b = row >> 11;       // NI = 2048
    const int i = row & (NI - 1);
    const float* drow = d_d2 + (size_t)b * NI * NI + (size_t)i * NI;

    float bd[KN];
    int   bix[KN];
#pragma unroll
    for (int k = 0; k < KN; k++) { bd[k] = 3.4e38f; bix[k] = 0x7fffffff; }

    for (int j = lane; j < NI; j += 32) {
        float dv = drow[j];
        if (dv < bd[KN - 1]) {                 // strict <: earlier j wins ties
            bd[KN - 1] = dv; bix[KN - 1] = j;
#pragma unroll
            for (int q = KN - 1; q > 0; q--) {
                if (bd[q] < bd[q - 1]) {
                    float tf = bd[q]; bd[q] = bd[q - 1]; bd[q - 1] = tf;
                    int ti = bix[q]; bix[q] = bix[q - 1]; bix[q - 1] = ti;
                }
            }
        }
    }

    __shared__ float sd[4][32 * KN];
    __shared__ int   si[4][32 * KN];
#pragma unroll
    for (int k = 0; k < KN; k++) {
        sd[w][lane * KN + k] = bd[k];
        si[w][lane * KN + k] = bix[k];
    }
    __syncwarp();
    if (lane == 0) {
        int* oi = d_idx + (size_t)row * KN;
        for (int k = 0; k < KN; k++) {
            float best = 3.5e38f; int bbi = 0x7fffffff; int bpos = 0;
            for (int t = 0; t < 32 * KN; t++) {
                float v = sd[w][t]; int ii = si[w][t];
                if (v < best || (v == best && ii < bbi)) { best = v; bbi = ii; bpos = t; }
            }
            oi[k] = bbi;
            sd[w][bpos] = 3.6e38f;
        }
    }
}

// ---------------------------------------------------------------------------
// EdgeConv: g[row,h] = max_k relu(P[row,h] - Q[row,h] + Q[nbr_k,h] + b_g[h])
// ---------------------------------------------------------------------------
__global__ void edgeconv_kernel(const float* __restrict__ bgv) {
    const int row = blockIdx.x;
    const int b = row >> 11;
    __shared__ int sj[KN];
    if (threadIdx.x < KN) sj[threadIdx.x] = d_idx[(size_t)row * KN + threadIdx.x];
    __syncthreads();
    const float* Pr = d_P + (size_t)row * HD;
    const float* Qr = d_Q + (size_t)row * HD;
    const float* Qb = d_Q + (size_t)b * NI * HD;
    float* gr = d_g + (size_t)row * HD;
    const float* q0 = Qb + (size_t)sj[0] * HD;
    const float* q1 = Qb + (size_t)sj[1] * HD;
    const float* q2 = Qb + (size_t)sj[2] * HD;
    const float* q3 = Qb + (size_t)sj[3] * HD;
    const float* q4 = Qb + (size_t)sj[4] * HD;
    for (int hh = threadIdx.x; hh < HD; hh += 128) {
        float base = Pr[hh] - Qr[hh] + bgv[hh];
        float m = fmaxf(base + q0[hh], 0.f);
        m = fmaxf(m, fmaxf(base + q1[hh], 0.f));
        m = fmaxf(m, fmaxf(base + q2[hh], 0.f));
        m = fmaxf(m, fmaxf(base + q3[hh], 0.f));
        m = fmaxf(m, fmaxf(base + q4[hh], 0.f));
        gr[hh] = m;
    }
}

__device__ __forceinline__ float blockReduceSum(float v, float* sh) {
    int lane = threadIdx.x & 31, w = threadIdx.x >> 5;
#pragma unroll
    for (int o = 16; o > 0; o >>= 1) v += __shfl_down_sync(0xffffffffu, v, o);
    if (lane == 0) sh[w] = v;
    __syncthreads();
    int nw = blockDim.x >> 5;
    v = (threadIdx.x < nw) ? sh[threadIdx.x] : 0.f;
    if (w == 0)
#pragma unroll
        for (int o = 16; o > 0; o >>= 1) v += __shfl_down_sync(0xffffffffu, v, o);
    return v;  // valid in thread 0
}

// ---------------------------------------------------------------------------
// Gated attention score: A_raw = sum_d tanh(Ap+ba)*sigmoid(Bp+bb)*Wc[d] + bc
// ---------------------------------------------------------------------------
__global__ void gate_kernel(const float* __restrict__ ba, const float* __restrict__ bb,
                            const float* __restrict__ Wc, const float* __restrict__ bc,
                            float* __restrict__ out) {
    const int row = blockIdx.x, tid = threadIdx.x;
    __shared__ float sh[32];
    const float* ap = d_Ap + (size_t)row * DA;
    const float* bp = d_Bp + (size_t)row * DA;
    float s = 0.f;
    for (int dd = tid; dd < DA; dd += 128) {
        float av = tanhf(ap[dd] + ba[dd]);
        float bv = bp[dd] + bb[dd];
        bv = 1.f / (1.f + expf(-bv));
        s += av * bv * Wc[dd];
    }
    s = blockReduceSum(s, sh);
    if (tid == 0) {
        float v = s + bc[0];
        d_Ar[row] = v;
        out[2 * NB * NC + row] = v;   // A_raw section of output
    }
}

// ---------------------------------------------------------------------------
// Per-bag softmax over N + weighted pooling: M[b,h] = sum_n softmax(Ar)[n]*g[n,h]
// ---------------------------------------------------------------------------
__global__ void pool_kernel() {
    const int b = blockIdx.x, tid = threadIdx.x;
    __shared__ float red[512];
    __shared__ float wsh[NI];
    __shared__ float smx, ssum;
    const float* Ar = d_Ar + (size_t)b * NI;

    float mx = -3.4e38f;
    for (int n = tid; n < NI; n += 512) mx = fmaxf(mx, Ar[n]);
    red[tid] = mx; __syncthreads();
    for (int s = 256; s > 0; s >>= 1) { if (tid < s) red[tid] = fmaxf(red[tid], red[tid + s]); __syncthreads(); }
    if (tid == 0) smx = red[0];
    __syncthreads();

    float sum = 0.f;
    for (int n = tid; n < NI; n += 512) { float e = expf(Ar[n] - smx); wsh[n] = e; sum += e; }
    red[tid] = sum; __syncthreads();
    for (int s = 256; s > 0; s >>= 1) { if (tid < s) red[tid] += red[tid + s]; __syncthreads(); }
    if (tid == 0) ssum = red[0];
    __syncthreads();

    const float* gb = d_g + (size_t)b * NI * HD;
    float acc = 0.f;
    for (int n = 0; n < NI; n++) acc = fmaf(wsh[n], gb[(size_t)n * HD + tid], acc);
    d_M[b * HD + tid] = acc / ssum;
}

// ---------------------------------------------------------------------------
// Head: logits = M @ W_cls + b_cls ; Y_prob = softmax(logits)
// ---------------------------------------------------------------------------
__global__ void head_kernel(const float* __restrict__ Wcls, const float* __restrict__ bcls,
                            float* __restrict__ out) {
    const int b = blockIdx.x, tid = threadIdx.x;
    __shared__ float sh[32];
    float s0 = 0.f, s1 = 0.f;
    for (int hh = tid; hh < HD; hh += 128) {
        float m = d_M[b * HD + hh];
        s0 = fmaf(m, Wcls[hh * NC + 0], s0);
        s1 = fmaf(m, Wcls[hh * NC + 1], s1);
    }
    s0 = blockReduceSum(s0, sh);
    __syncthreads();
    s1 = blockReduceSum(s1, sh);
    if (tid == 0) {
        float l0 = s0 + bcls[0], l1 = s1 + bcls[1];
        out[b * NC + 0] = l0;
        out[b * NC + 1] = l1;
        float mx = fmaxf(l0, l1);
        float e0 = expf(l0 - mx), e1 = expf(l1 - mx);
        float inv = 1.f / (e0 + e1);
        out[NB * NC + b * NC + 0] = e0 * inv;
        out[NB * NC + b * NC + 1] = e1 * inv;
    }
}

// ---------------------------------------------------------------------------
extern "C" void kernel_launch(void* const* d_in, const int* in_sizes, int n_in,
                              void* d_out, int out_size) {
    const float* h     = (const float*)d_in[0];
    const float* W_fc  = (const float*)d_in[1];
    const float* b_fc  = (const float*)d_in[2];
    const float* W_g   = (const float*)d_in[3];
    const float* b_g   = (const float*)d_in[4];
    const float* W_a   = (const float*)d_in[5];
    const float* b_a   = (const float*)d_in[6];
    const float* W_b   = (const float*)d_in[7];
    const float* b_b   = (const float*)d_in[8];
    const float* W_c   = (const float*)d_in[9];
    const float* b_c   = (const float*)d_in[10];
    const float* W_cls = (const float*)d_in[11];
    const float* b_cls = (const float*)d_in[12];
    float* out = (float*)d_out;

    void *px, *pP, *pQ, *pg, *pAp, *pBp;
    cudaGetSymbolAddress(&px, d_x);
    cudaGetSymbolAddress(&pP, d_P);
    cudaGetSymbolAddress(&pQ, d_Q);
    cudaGetSymbolAddress(&pg, d_g);
    cudaGetSymbolAddress(&pAp, d_Ap);
    cudaGetSymbolAddress(&pBp, d_Bp);
    float* x  = (float*)px;
    float* P  = (float*)pP;
    float* Q  = (float*)pQ;
    float* g  = (float*)pg;
    float* Ap = (float*)pAp;
    float* Bp = (float*)pBp;

    const int M = NB * NI;  // 16384

    // 1. x = relu(h @ W_fc + b_fc)
    gemm_bias_kernel<1><<<dim3(HD / 64, M / 64), 256>>>(h, W_fc, b_fc, x, M, DIM, HD);
    // 2. squared norms
    sqnorm_kernel<<<M, 128>>>();
    // 3. pairwise distances (per bag)
    gram_d2_kernel<<<dim3(NI / 64, NI / 64, NB), 256>>>();
    // 4. top-K neighbors
    topk_kernel<<<M / 4, 128>>>();
    // 5/6. P = x@Wg_top, Q = x@Wg_bot  (EdgeConv decomposition)
    gemm_bias_kernel<0><<<dim3(HD / 64, M / 64), 256>>>(x, W_g, nullptr, P, M, HD, HD);
    gemm_bias_kernel<0><<<dim3(HD / 64, M / 64), 256>>>(x, W_g + (size_t)HD * HD, nullptr, Q, M, HD, HD);
    // 7. edgeconv gather + max
    edgeconv_kernel<<<M, 128>>>(b_g);
    // 8/9. attention pre-projections
    gemm_bias_kernel<0><<<dim3(DA / 64, M / 64), 256>>>(g, W_a, nullptr, Ap, M, HD, DA);
    gemm_bias_kernel<0><<<dim3(DA / 64, M / 64), 256>>>(g, W_b, nullptr, Bp, M, HD, DA);
    // 10. gated attention score -> A_raw
    gate_kernel<<<M, 128>>>(b_a, b_b, W_c, b_c, out);
    // 11. softmax over instances + pooling
    pool_kernel<<<NB, 512>>>();
    // 12. classifier head + Y_prob
    head_kernel<<<NB, 128>>>(W_cls, b_cls, out);
}

// round 2
// speedup vs baseline: 4.4204x; 4.4204x over previous
#include <cuda_runtime.h>
#include <math.h>
#include <cstdint>

constexpr int NB  = 8;
constexpr int NI  = 2048;
constexpr int DIM = 1024;
constexpr int HD  = 512;
constexpr int DA  = 256;
constexpr int KN  = 5;
constexpr int NC  = 2;
constexpr int MROWS = NB * NI;   // 16384

// Scratch (static device globals)
__device__ float d_x [MROWS * HD];
__device__ float d_sq[MROWS];
__device__ float d_d2[(size_t)NB * NI * NI];   // 128 MB
__device__ int   d_idx[MROWS * KN];
__device__ float d_P [MROWS * HD];
__device__ float d_Q [MROWS * HD];
__device__ float d_g [MROWS * HD];
__device__ float d_Ap[MROWS * DA];
__device__ float d_Bp[MROWS * DA];
__device__ float d_Ar[MROWS];
__device__ float d_M [NB * HD];

// ---------------------------------------------------------------------------
// High-throughput fp32 GEMM: 128x128 block tile, BK=8, 256 threads, 8x8/thread,
// double-buffered smem, float4 loads. Split-tile register layout:
//   rows {ty*4..+3, 64+ty*4..+3}, cols {tx*4..+3, 64+tx*4..+3}
// EPI: 0 = C=A@B(+bias), 1 = relu(A@B+bias), 2 = gram->d2 with symmetric mirror
// TRB: B given row-major [N x K] (use B[n][k])
// ---------------------------------------------------------------------------
constexpr int BM = 128, BN = 128, BK = 8;

template <int EPI, int TRB>
__global__ __launch_bounds__(256, 2)
void gemm128(const float* __restrict__ Aall, const float* __restrict__ Ball,
             const float* __restrict__ bias, float* __restrict__ Call,
             int M, int Kd, int Nd) {
    const float* A = Aall;
    const float* B = Ball;
    float* C = Call;
    const float* sqb = nullptr;
    const int bx = blockIdx.x, by = blockIdx.y;
    if (EPI == 2) {
        if (by > bx) return;                       // symmetric: upper blocks only
        const int bag = blockIdx.z;
        A = Aall + (size_t)bag * NI * HD;
        B = A;
        C = Call + (size_t)bag * NI * NI;
        sqb = d_sq + bag * NI;
    }
    const int rowBase = by * BM, colBase = bx * BN;

    __shared__ float As[2][BK][BM];
    __shared__ float Bs[2][BK][BN];

    const int tid = threadIdx.x;
    const int tx = tid & 15, ty = tid >> 4;
    const int arow = tid >> 1, acol = (tid & 1) * 4;     // A / TRB-B staging
    const int brow = tid >> 5, bcol = (tid & 31) * 4;    // normal-B staging

    // Prologue: load k-tile 0
    float4 aR = *(const float4*)(A + (size_t)(rowBase + arow) * Kd + acol);
    float4 bR = TRB ? *(const float4*)(B + (size_t)(colBase + arow) * Kd + acol)
                    : *(const float4*)(B + (size_t)brow * Nd + colBase + bcol);
    As[0][acol + 0][arow] = aR.x; As[0][acol + 1][arow] = aR.y;
    As[0][acol + 2][arow] = aR.z; As[0][acol + 3][arow] = aR.w;
    if (TRB) {
        Bs[0][acol + 0][arow] = bR.x; Bs[0][acol + 1][arow] = bR.y;
        Bs[0][acol + 2][arow] = bR.z; Bs[0][acol + 3][arow] = bR.w;
    } else {
        *(float4*)&Bs[0][brow][bcol] = bR;
    }
    __syncthreads();

    float acc[8][8];
#pragma unroll
    for (int m = 0; m < 8; m++)
#pragma unroll
        for (int n = 0; n < 8; n++) acc[m][n] = 0.f;

    const int KT = Kd / BK;
    for (int kt = 0; kt < KT; kt++) {
        const int cur = kt & 1;
        if (kt + 1 < KT) {
            const int k0 = (kt + 1) * BK;
            aR = *(const float4*)(A + (size_t)(rowBase + arow) * Kd + k0 + acol);
            bR = TRB ? *(const float4*)(B + (size_t)(colBase + arow) * Kd + k0 + acol)
                     : *(const float4*)(B + (size_t)(k0 + brow) * Nd + colBase + bcol);
        }
#pragma unroll
        for (int kk = 0; kk < BK; kk++) {
            float4 a0 = *(const float4*)&As[cur][kk][ty * 4];
            float4 a1 = *(const float4*)&As[cur][kk][64 + ty * 4];
            float4 b0 = *(const float4*)&Bs[cur][kk][tx * 4];
            float4 b1 = *(const float4*)&Bs[cur][kk][64 + tx * 4];
            float av[8] = {a0.x, a0.y, a0.z, a0.w, a1.x, a1.y, a1.z, a1.w};
            float bv[8] = {b0.x, b0.y, b0.z, b0.w, b1.x, b1.y, b1.z, b1.w};
#pragma unroll
            for (int m = 0; m < 8; m++)
#pragma unroll
                for (int n = 0; n < 8; n++)
                    acc[m][n] = fmaf(av[m], bv[n], acc[m][n]);
        }
        if (kt + 1 < KT) {
            const int nxt = cur ^ 1;
            As[nxt][acol + 0][arow] = aR.x; As[nxt][acol + 1][arow] = aR.y;
            As[nxt][acol + 2][arow] = aR.z; As[nxt][acol + 3][arow] = aR.w;
            if (TRB) {
                Bs[nxt][acol + 0][arow] = bR.x; Bs[nxt][acol + 1][arow] = bR.y;
                Bs[nxt][acol + 2][arow] = bR.z; Bs[nxt][acol + 3][arow] = bR.w;
            } else {
                *(float4*)&Bs[nxt][brow][bcol] = bR;
            }
            __syncthreads();
        }
    }

    // Epilogue
    int rIdx[8];
#pragma unroll
    for (int m = 0; m < 8; m++)
        rIdx[m] = rowBase + ((m < 4) ? (ty * 4 + m) : (64 + ty * 4 + (m - 4)));
    const int c0 = colBase + tx * 4;
    const int c1 = colBase + 64 + tx * 4;

    if (EPI == 2) {
        float sqc[8];
#pragma unroll
        for (int n = 0; n < 4; n++) { sqc[n] = sqb[c0 + n]; sqc[4 + n] = sqb[c1 + n]; }
#pragma unroll
        for (int m = 0; m < 8; m++) {
            const float sr = sqb[rIdx[m]];
            float4 v0, v1;
            v0.x = sr + sqc[0] - 2.f * acc[m][0];
            v0.y = sr + sqc[1] - 2.f * acc[m][1];
            v0.z = sr + sqc[2] - 2.f * acc[m][2];
            v0.w = sr + sqc[3] - 2.f * acc[m][3];
            v1.x = sr + sqc[4] - 2.f * acc[m][4];
            v1.y = sr + sqc[5] - 2.f * acc[m][5];
            v1.z = sr + sqc[6] - 2.f * acc[m][6];
            v1.w = sr + sqc[7] - 2.f * acc[m][7];
            *(float4*)&C[(size_t)rIdx[m] * Nd + c0] = v0;
            *(float4*)&C[(size_t)rIdx[m] * Nd + c1] = v1;
        }
        if (bx != by) {  // mirror (transposed) store; rows within thread are contiguous x4
            const int r0 = rowBase + ty * 4;
            const int r1 = rowBase + 64 + ty * 4;
#pragma unroll
            for (int n = 0; n < 8; n++) {
                const int c = (n < 4) ? (c0 + n) : (c1 + (n - 4));
                const float sc = sqc[n];
                float4 w0, w1;
                w0.x = sc + sqb[rIdx[0]] - 2.f * acc[0][n];
                w0.y = sc + sqb[rIdx[1]] - 2.f * acc[1][n];
                w0.z = sc + sqb[rIdx[2]] - 2.f * acc[2][n];
                w0.w = sc + sqb[rIdx[3]] - 2.f * acc[3][n];
                w1.x = sc + sqb[rIdx[4]] - 2.f * acc[4][n];
                w1.y = sc + sqb[rIdx[5]] - 2.f * acc[5][n];
                w1.z = sc + sqb[rIdx[6]] - 2.f * acc[6][n];
                w1.w = sc + sqb[rIdx[7]] - 2.f * acc[7][n];
                *(float4*)&C[(size_t)c * Nd + r0] = w0;
                *(float4*)&C[(size_t)c * Nd + r1] = w1;
            }
        }
    } else {
        float bb0[4] = {0.f, 0.f, 0.f, 0.f}, bb1[4] = {0.f, 0.f, 0.f, 0.f};
        if (bias) {
            float4 t0 = *(const float4*)&bias[c0];
            float4 t1 = *(const float4*)&bias[c1];
            bb0[0] = t0.x; bb0[1] = t0.y; bb0[2] = t0.z; bb0[3] = t0.w;
            bb1[0] = t1.x; bb1[1] = t1.y; bb1[2] = t1.z; bb1[3] = t1.w;
        }
#pragma unroll
        for (int m = 0; m < 8; m++) {
            float4 v0, v1;
            v0.x = acc[m][0] + bb0[0]; v0.y = acc[m][1] + bb0[1];
            v0.z = acc[m][2] + bb0[2]; v0.w = acc[m][3] + bb0[3];
            v1.x = acc[m][4] + bb1[0]; v1.y = acc[m][5] + bb1[1];
            v1.z = acc[m][6] + bb1[2]; v1.w = acc[m][7] + bb1[3];
            if (EPI == 1) {
                v0.x = fmaxf(v0.x, 0.f); v0.y = fmaxf(v0.y, 0.f);
                v0.z = fmaxf(v0.z, 0.f); v0.w = fmaxf(v0.w, 0.f);
                v1.x = fmaxf(v1.x, 0.f); v1.y = fmaxf(v1.y, 0.f);
                v1.z = fmaxf(v1.z, 0.f); v1.w = fmaxf(v1.w, 0.f);
            }
            *(float4*)&C[(size_t)rIdx[m] * Nd + c0] = v0;
            *(float4*)&C[(size_t)rIdx[m] * Nd + c1] = v1;
        }
    }
}

// ---------------------------------------------------------------------------
// Row squared norms (one block of 128 per row, float4)
// ---------------------------------------------------------------------------
__global__ void sqnorm_kernel() {
    const int row = blockIdx.x, tid = threadIdx.x;
    __shared__ float sh[4];
    const float* xr = d_x + (size_t)row * HD;
    float4 v = *(const float4*)(xr + tid * 4);
    float s = v.x * v.x + v.y * v.y + v.z * v.z + v.w * v.w;
    const int lane = tid & 31, w = tid >> 5;
#pragma unroll
    for (int o = 16; o > 0; o >>= 1) s += __shfl_down_sync(0xffffffffu, s, o);
    if (lane == 0) sh[w] = s;
    __syncthreads();
    if (tid == 0) d_sq[row] = sh[0] + sh[1] + sh[2] + sh[3];
}

// ---------------------------------------------------------------------------
// Top-K smallest per row. Warp per row, float4 reads, parallel argmin merge.
// Tie-break: smaller index (matches jax top_k on -d2).
// ---------------------------------------------------------------------------
__global__ void topk_kernel() {
    const int w = threadIdx.x >> 5;
    const int lane = threadIdx.x & 31;
    const int row = blockIdx.x * 4 + w;
    const int b = row >> 11;
    const int i = row & (NI - 1);
    const float* drow = d_d2 + (size_t)b * NI * NI + (size_t)i * NI;

    float bd[KN]; int bix[KN];
#pragma unroll
    for (int k = 0; k < KN; k++) { bd[k] = 3.4e38f; bix[k] = 0x7fffffff; }

    for (int j0 = lane * 4; j0 < NI; j0 += 128) {
        float4 dv = *(const float4*)(drow + j0);
        float vs[4] = {dv.x, dv.y, dv.z, dv.w};
#pragma unroll
        for (int t = 0; t < 4; t++) {
            float v = vs[t];
            if (v < bd[KN - 1]) {
                bd[KN - 1] = v; bix[KN - 1] = j0 + t;
#pragma unroll
                for (int q = KN - 1; q > 0; q--) {
                    if (bd[q] < bd[q - 1]) {
                        float tf = bd[q]; bd[q] = bd[q - 1]; bd[q - 1] = tf;
                        int ti = bix[q]; bix[q] = bix[q - 1]; bix[q - 1] = ti;
                    }
                }
            }
        }
    }

    // Parallel 5-round warp argmin merge
    int* oi = d_idx + (size_t)row * KN;
    int cp = 0;
    float cv = bd[0]; int ci = bix[0];
#pragma unroll
    for (int k = 0; k < KN; k++) {
        float rv = cv; int ri = ci;
#pragma unroll
        for (int off = 16; off > 0; off >>= 1) {
            float ov = __shfl_xor_sync(0xffffffffu, rv, off);
            int   oj = __shfl_xor_sync(0xffffffffu, ri, off);
            if (ov < rv || (ov == rv && oj < ri)) { rv = ov; ri = oj; }
        }
        if (lane == 0) oi[k] = ri;
        if (cv == rv && ci == ri) {   // this lane won: advance its pointer
            cp++;
            float nv = 3.4e38f; int ni2 = 0x7fffffff;
#pragma unroll
            for (int q = 1; q < KN; q++) if (cp == q) { nv = bd[q]; ni2 = bix[q]; }
            cv = nv; ci = ni2;
        }
    }
}

// ---------------------------------------------------------------------------
// EdgeConv: g[row,h] = max_k relu(P - Q + b_g + Q[nbr_k])   (relu folds: init 0)
// ---------------------------------------------------------------------------
__global__ void edgeconv_kernel(const float* __restrict__ bgv) {
    const int row = blockIdx.x;
    const int b = row >> 11;
    const int tid = threadIdx.x;       // 128 threads, float4 each
    __shared__ int sj[KN];
    if (tid < KN) sj[tid] = d_idx[(size_t)row * KN + tid];
    __syncthreads();
    const int hh = tid * 4;
    float4 p  = *(const float4*)(d_P + (size_t)row * HD + hh);
    float4 q  = *(const float4*)(d_Q + (size_t)row * HD + hh);
    float4 bg = *(const float4*)(bgv + hh);
    float bx_ = p.x - q.x + bg.x;
    float by_ = p.y - q.y + bg.y;
    float bz_ = p.z - q.z + bg.z;
    float bw_ = p.w - q.w + bg.w;
    float mx = 0.f, my = 0.f, mz = 0.f, mw = 0.f;
    const float* Qb = d_Q + (size_t)b * NI * HD;
#pragma unroll
    for (int k = 0; k < KN; k++) {
        float4 qk = *(const float4*)(Qb + (size_t)sj[k] * HD + hh);
        mx = fmaxf(mx, bx_ + qk.x);
        my = fmaxf(my, by_ + qk.y);
        mz = fmaxf(mz, bz_ + qk.z);
        mw = fmaxf(mw, bw_ + qk.w);
    }
    float4 o; o.x = mx; o.y = my; o.z = mz; o.w = mw;
    *(float4*)(d_g + (size_t)row * HD + hh) = o;
}

__device__ __forceinline__ float blockReduceSum(float v, float* sh) {
    int lane = threadIdx.x & 31, w = threadIdx.x >> 5;
#pragma unroll
    for (int o = 16; o > 0; o >>= 1) v += __shfl_down_sync(0xffffffffu, v, o);
    if (lane == 0) sh[w] = v;
    __syncthreads();
    int nw = blockDim.x >> 5;
    v = (threadIdx.x < nw) ? sh[threadIdx.x] : 0.f;
    if (w == 0)
#pragma unroll
        for (int o = 16; o > 0; o >>= 1) v += __shfl_down_sync(0xffffffffu, v, o);
    return v;
}

// ---------------------------------------------------------------------------
// Gated attention score -> A_raw (also writes output section)
// ---------------------------------------------------------------------------
__global__ void gate_kernel(const float* __restrict__ ba, const float* __restrict__ bb,
                            const float* __restrict__ Wc, const float* __restrict__ bc,
                            float* __restrict__ out) {
    const int row = blockIdx.x, tid = threadIdx.x;
    __shared__ float sh[32];
    const float* ap = d_Ap + (size_t)row * DA;
    const float* bp = d_Bp + (size_t)row * DA;
    float s = 0.f;
    for (int dd = tid; dd < DA; dd += 128) {
        float av = tanhf(ap[dd] + ba[dd]);
        float bv = bp[dd] + bb[dd];
        bv = 1.f / (1.f + expf(-bv));
        s += av * bv * Wc[dd];
    }
    s = blockReduceSum(s, sh);
    if (tid == 0) {
        float v = s + bc[0];
        d_Ar[row] = v;
        out[2 * NB * NC + row] = v;
    }
}

// ---------------------------------------------------------------------------
// Per-bag softmax stats: overwrite d_Ar with normalized weights; zero d_M.
// ---------------------------------------------------------------------------
__global__ void attn_stats_kernel() {
    const int b = blockIdx.x, tid = threadIdx.x;   // 512 threads
    __shared__ float red[512];
    float* Ar = d_Ar + (size_t)b * NI;

    float mx = -3.4e38f;
    for (int n = tid; n < NI; n += 512) mx = fmaxf(mx, Ar[n]);
    red[tid] = mx; __syncthreads();
    for (int s = 256; s > 0; s >>= 1) { if (tid < s) red[tid] = fmaxf(red[tid], red[tid + s]); __syncthreads(); }
    mx = red[0];
    __syncthreads();

    float sum = 0.f;
    for (int n = tid; n < NI; n += 512) sum += expf(Ar[n] - mx);
    red[tid] = sum; __syncthreads();
    for (int s = 256; s > 0; s >>= 1) { if (tid < s) red[tid] += red[tid + s]; __syncthreads(); }
    const float inv = 1.f / red[0];
    __syncthreads();

    for (int n = tid; n < NI; n += 512) Ar[n] = expf(Ar[n] - mx) * inv;
    d_M[b * HD + tid] = 0.f;   // 512 == HD
}

// ---------------------------------------------------------------------------
// Chunked weighted pooling with atomics: grid (NB, 16), 256 threads
// ---------------------------------------------------------------------------
__global__ void pool_acc_kernel() {
    const int b = blockIdx.x, ch = blockIdx.y, tid = threadIdx.x;
    const float* w  = d_Ar + (size_t)b * NI + ch * 128;
    const float* gb = d_g + ((size_t)b * NI + (size_t)ch * 128) * HD;
    __shared__ float ws[128];
    if (tid < 128) ws[tid] = w[tid];
    __syncthreads();
    const int c0 = tid, c1 = tid + 256;
    float a0 = 0.f, a1 = 0.f;
    for (int n = 0; n < 128; n++) {
        const float wn = ws[n];
        a0 = fmaf(wn, gb[(size_t)n * HD + c0], a0);
        a1 = fmaf(wn, gb[(size_t)n * HD + c1], a1);
    }
    atomicAdd(&d_M[b * HD + c0], a0);
    atomicAdd(&d_M[b * HD + c1], a1);
}

// ---------------------------------------------------------------------------
// Classifier head + Y_prob
// ---------------------------------------------------------------------------
__global__ void head_kernel(const float* __restrict__ Wcls, const float* __restrict__ bcls,
                            float* __restrict__ out) {
    const int b = blockIdx.x, tid = threadIdx.x;
    __shared__ float sh[32];
    float s0 = 0.f, s1 = 0.f;
    for (int hh = tid; hh < HD; hh += 128) {
        float m = d_M[b * HD + hh];
        s0 = fmaf(m, Wcls[hh * NC + 0], s0);
        s1 = fmaf(m, Wcls[hh * NC + 1], s1);
    }
    s0 = blockReduceSum(s0, sh);
    __syncthreads();
    s1 = blockReduceSum(s1, sh);
    if (tid == 0) {
        float l0 = s0 + bcls[0], l1 = s1 + bcls[1];
        out[b * NC + 0] = l0;
        out[b * NC + 1] = l1;
        float mx = fmaxf(l0, l1);
        float e0 = expf(l0 - mx), e1 = expf(l1 - mx);
        float inv = 1.f / (e0 + e1);
        out[NB * NC + b * NC + 0] = e0 * inv;
        out[NB * NC + b * NC + 1] = e1 * inv;
    }
}

// ---------------------------------------------------------------------------
extern "C" void kernel_launch(void* const* d_in, const int* in_sizes, int n_in,
                              void* d_out, int out_size) {
    const float* h     = (const float*)d_in[0];
    const float* W_fc  = (const float*)d_in[1];
    const float* b_fc  = (const float*)d_in[2];
    const float* W_g   = (const float*)d_in[3];
    const float* b_g   = (const float*)d_in[4];
    const float* W_a   = (const float*)d_in[5];
    const float* b_a   = (const float*)d_in[6];
    const float* W_b   = (const float*)d_in[7];
    const float* b_b   = (const float*)d_in[8];
    const float* W_c   = (const float*)d_in[9];
    const float* b_c   = (const float*)d_in[10];
    const float* W_cls = (const float*)d_in[11];
    const float* b_cls = (const float*)d_in[12];
    float* out = (float*)d_out;

    void *px, *pP, *pQ, *pg, *pAp, *pBp, *pd2;
    cudaGetSymbolAddress(&px, d_x);
    cudaGetSymbolAddress(&pP, d_P);
    cudaGetSymbolAddress(&pQ, d_Q);
    cudaGetSymbolAddress(&pg, d_g);
    cudaGetSymbolAddress(&pAp, d_Ap);
    cudaGetSymbolAddress(&pBp, d_Bp);
    cudaGetSymbolAddress(&pd2, d_d2);
    float* x  = (float*)px;
    float* P  = (float*)pP;
    float* Q  = (float*)pQ;
    float* g  = (float*)pg;
    float* Ap = (float*)pAp;
    float* Bp = (float*)pBp;
    float* d2 = (float*)pd2;

    // 1. x = relu(h @ W_fc + b_fc)            [16384,1024]@[1024,512]
    gemm128<1, 0><<<dim3(HD / BN, MROWS / BM), 256>>>(h, W_fc, b_fc, x, MROWS, DIM, HD);
    // 2. squared norms
    sqnorm_kernel<<<MROWS, 128>>>();
    // 3. per-bag Gram -> d2 (symmetric, upper blocks + mirror)
    gemm128<2, 1><<<dim3(NI / BN, NI / BM, NB), 256>>>(x, x, nullptr, d2, NI, HD, NI);
    // 4. top-K neighbors
    topk_kernel<<<MROWS / 4, 128>>>();
    // 5/6. EdgeConv decomposition: P = x@Wg_top, Q = x@Wg_bot
    gemm128<0, 0><<<dim3(HD / BN, MROWS / BM), 256>>>(x, W_g, nullptr, P, MROWS, HD, HD);
    gemm128<0, 0><<<dim3(HD / BN, MROWS / BM), 256>>>(x, W_g + (size_t)HD * HD, nullptr, Q, MROWS, HD, HD);
    // 7. edgeconv gather + max
    edgeconv_kernel<<<MROWS, 128>>>(b_g);
    // 8/9. attention pre-projections
    gemm128<0, 0><<<dim3(DA / BN, MROWS / BM), 256>>>(g, W_a, nullptr, Ap, MROWS, HD, DA);
    gemm128<0, 0><<<dim3(DA / BN, MROWS / BM), 256>>>(g, W_b, nullptr, Bp, MROWS, HD, DA);
    // 10. gated attention score -> A_raw (+ output section)
    gate_kernel<<<MROWS, 128>>>(b_a, b_b, W_c, b_c, out);
    // 11. softmax stats (normalized weights in-place) + zero M
    attn_stats_kernel<<<NB, 512>>>();
    // 12. chunked weighted pooling
    pool_acc_kernel<<<dim3(NB, 16), 256>>>();
    // 13. classifier head + Y_prob
    head_kernel<<<NB, 128>>>(W_cls, b_cls, out);
}

// round 8
// speedup vs baseline: 4.4485x; 1.0064x over previous
#include <cuda_runtime.h>
#include <math.h>
#include <cstdint>

constexpr int NB  = 8;
constexpr int NI  = 2048;
constexpr int DIM = 1024;
constexpr int HD  = 512;
constexpr int DA  = 256;
constexpr int KN  = 5;
constexpr int KC  = 9;      // candidate count for exact re-rank
constexpr int NC  = 2;
constexpr int MROWS = NB * NI;   // 16384

// Scratch (static device globals)
__device__ float d_x [MROWS * HD];
__device__ float d_sq[MROWS];
__device__ float d_d2[(size_t)NB * NI * NI];   // 128 MB (approx, tf32)
__device__ int   d_cand[MROWS * KC];
__device__ int   d_idx[MROWS * KN];
__device__ float d_P [MROWS * HD];
__device__ float d_Q [MROWS * HD];
__device__ float d_g [MROWS * HD];
__device__ float d_Ap[MROWS * DA];
__device__ float d_Bp[MROWS * DA];
__device__ float d_Ar[MROWS];
__device__ float d_M [NB * HD];

// ===========================================================================
// PART 1: fp32 FFMA GEMM (round-2 proven) — used ONLY for the fc layer,
// whose output x feeds the kNN discrete decision and must be fp32-exact.
// 128x128x8 tile, 256 threads, 8x8/thread, double-buffered.
// ===========================================================================
constexpr int FBM = 128, FBN = 128, FBK = 8;

__global__ __launch_bounds__(256, 2)
void gemm_f32_relu(const float* __restrict__ A, const float* __restrict__ Bm,
                   const float* __restrict__ bias, float* __restrict__ Cm,
                   int M, int Kd, int Nd) {
    __shared__ float As[2][FBK][FBM];
    __shared__ float Bs[2][FBK][FBN];
    const int tid = threadIdx.x;
    const int tx = tid & 15, ty = tid >> 4;
    const int rowBase = blockIdx.y * FBM;
    const int colBase = blockIdx.x * FBN;
    const int arow = tid >> 1, acol = (tid & 1) * 4;
    const int brow = tid >> 5, bcol = (tid & 31) * 4;

    float4 aR = *(const float4*)(A + (size_t)(rowBase + arow) * Kd + acol);
    float4 bR = *(const float4*)(Bm + (size_t)brow * Nd + colBase + bcol);
    As[0][acol + 0][arow] = aR.x; As[0][acol + 1][arow] = aR.y;
    As[0][acol + 2][arow] = aR.z; As[0][acol + 3][arow] = aR.w;
    *(float4*)&Bs[0][brow][bcol] = bR;
    __syncthreads();

    float acc[8][8];
#pragma unroll
    for (int m = 0; m < 8; m++)
#pragma unroll
        for (int n = 0; n < 8; n++) acc[m][n] = 0.f;

    const int KT = Kd / FBK;
    for (int kt = 0; kt < KT; kt++) {
        const int cur = kt & 1;
        if (kt + 1 < KT) {
            const int k0 = (kt + 1) * FBK;
            aR = *(const float4*)(A + (size_t)(rowBase + arow) * Kd + k0 + acol);
            bR = *(const float4*)(Bm + (size_t)(k0 + brow) * Nd + colBase + bcol);
        }
#pragma unroll
        for (int kk = 0; kk < FBK; kk++) {
            float4 a0 = *(const float4*)&As[cur][kk][ty * 4];
            float4 a1 = *(const float4*)&As[cur][kk][64 + ty * 4];
            float4 b0 = *(const float4*)&Bs[cur][kk][tx * 4];
            float4 b1 = *(const float4*)&Bs[cur][kk][64 + tx * 4];
            float av[8] = {a0.x, a0.y, a0.z, a0.w, a1.x, a1.y, a1.z, a1.w};
            float bv[8] = {b0.x, b0.y, b0.z, b0.w, b1.x, b1.y, b1.z, b1.w};
#pragma unroll
            for (int m = 0; m < 8; m++)
#pragma unroll
                for (int n = 0; n < 8; n++)
                    acc[m][n] = fmaf(av[m], bv[n], acc[m][n]);
        }
        if (kt + 1 < KT) {
            const int nxt = cur ^ 1;
            As[nxt][acol + 0][arow] = aR.x; As[nxt][acol + 1][arow] = aR.y;
            As[nxt][acol + 2][arow] = aR.z; As[nxt][acol + 3][arow] = aR.w;
            *(float4*)&Bs[nxt][brow][bcol] = bR;
            __syncthreads();
        }
    }

#pragma unroll
    for (int m = 0; m < 8; m++) {
        const int r = rowBase + ((m < 4) ? (ty * 4 + m) : (64 + ty * 4 + (m - 4)));
        const int c0 = colBase + tx * 4;
        const int c1 = colBase + 64 + tx * 4;
        float4 t0 = *(const float4*)&bias[c0];
        float4 t1 = *(const float4*)&bias[c1];
        float4 v0, v1;
        v0.x = fmaxf(acc[m][0] + t0.x, 0.f); v0.y = fmaxf(acc[m][1] + t0.y, 0.f);
        v0.z = fmaxf(acc[m][2] + t0.z, 0.f); v0.w = fmaxf(acc[m][3] + t0.w, 0.f);
        v1.x = fmaxf(acc[m][4] + t1.x, 0.f); v1.y = fmaxf(acc[m][5] + t1.y, 0.f);
        v1.z = fmaxf(acc[m][6] + t1.z, 0.f); v1.w = fmaxf(acc[m][7] + t1.w, 0.f);
        *(float4*)&Cm[(size_t)r * Nd + c0] = v0;
        *(float4*)&Cm[(size_t)r * Nd + c1] = v1;
    }
}

// ===========================================================================
// PART 2: tf32-3x tensor-core GEMM (rna split) — Gram + smooth projections.
// EPI: 0 = A@B, 2 = per-bag Gram -> d2 + mirror. TRB: B row-major [Nd x Kd].
// ===========================================================================
constexpr int BM = 128, BN = 128, BK = 16;

__device__ __forceinline__ unsigned tf32_split(float a, float& lo) {
    float h;
    asm("cvt.rna.tf32.f32 %0, %1;\n" : "=f"(h) : "f"(a));
    lo = a - h;
    return __float_as_uint(h);
}

__device__ __forceinline__ void mma_tf32(float* c, unsigned a0, unsigned a1,
                                         unsigned a2, unsigned a3,
                                         unsigned b0, unsigned b1) {
    asm volatile(
        "mma.sync.aligned.m16n8k8.row.col.f32.tf32.tf32.f32 "
        "{%0,%1,%2,%3}, {%4,%5,%6,%7}, {%8,%9}, {%0,%1,%2,%3};\n"
        : "+f"(c[0]), "+f"(c[1]), "+f"(c[2]), "+f"(c[3])
        : "r"(a0), "r"(a1), "r"(a2), "r"(a3), "r"(b0), "r"(b1));
}

template <int EPI, int TRB>
__global__ __launch_bounds__(256, 2)
void gemm_tc(const float* __restrict__ Aall, const float* __restrict__ Ball,
             float* __restrict__ Call, int M, int Kd, int Nd) {
    const int bx = blockIdx.x, by = blockIdx.y;
    const float* A = Aall;
    const float* B = Ball;
    float* C = Call;
    const float* sqb = nullptr;
    if (EPI == 2) {
        if (by > bx) return;                        // symmetric: upper blocks only
        const int bag = blockIdx.z;
        A = Aall + (size_t)bag * NI * HD;
        B = A;
        C = Call + (size_t)bag * NI * NI;
        sqb = d_sq + bag * NI;
    }
    const int rowBase = by * BM, colBase = bx * BN;

    __shared__ float As[2][BK][BM + 8];
    __shared__ float Bs[2][BK][BN + 8];

    const int tid = threadIdx.x;
    const int lane = tid & 31;
    const int grp = lane >> 2;
    const int tig = lane & 3;
    const int warpId = tid >> 5;
    const int wm = (warpId & 1) * 64;
    const int wn = (warpId >> 1) * 32;

    const int ar = tid >> 2;
    const int ac = (tid & 3) * 4;
    const int br = tid >> 5;
    const int bc = (tid & 31) * 4;
    const int tn = tid >> 2;
    const int tk = (tid & 3) * 4;

    float4 pa0 = *(const float4*)(A + (size_t)(rowBase + ar) * Kd + ac);
    float4 pa1 = *(const float4*)(A + (size_t)(rowBase + ar + 64) * Kd + ac);
    float4 pb0, pb1;
    if (TRB) {
        pb0 = *(const float4*)(B + (size_t)(colBase + tn) * Kd + tk);
        pb1 = *(const float4*)(B + (size_t)(colBase + tn + 64) * Kd + tk);
    } else {
        pb0 = *(const float4*)(B + (size_t)br * Nd + colBase + bc);
        pb1 = *(const float4*)(B + (size_t)(br + 8) * Nd + colBase + bc);
    }
    {
        As[0][ac + 0][ar] = pa0.x; As[0][ac + 1][ar] = pa0.y;
        As[0][ac + 2][ar] = pa0.z; As[0][ac + 3][ar] = pa0.w;
        As[0][ac + 0][ar + 64] = pa1.x; As[0][ac + 1][ar + 64] = pa1.y;
        As[0][ac + 2][ar + 64] = pa1.z; As[0][ac + 3][ar + 64] = pa1.w;
        if (TRB) {
            Bs[0][tk + 0][tn] = pb0.x; Bs[0][tk + 1][tn] = pb0.y;
            Bs[0][tk + 2][tn] = pb0.z; Bs[0][tk + 3][tn] = pb0.w;
            Bs[0][tk + 0][tn + 64] = pb1.x; Bs[0][tk + 1][tn + 64] = pb1.y;
            Bs[0][tk + 2][tn + 64] = pb1.z; Bs[0][tk + 3][tn + 64] = pb1.w;
        } else {
            *(float4*)&Bs[0][br][bc] = pb0;
            *(float4*)&Bs[0][br + 8][bc] = pb1;
        }
    }
    __syncthreads();

    float acc[4][4][4];
#pragma unroll
    for (int mi = 0; mi < 4; mi++)
#pragma unroll
        for (int ni = 0; ni < 4; ni++)
#pragma unroll
            for (int q = 0; q < 4; q++) acc[mi][ni][q] = 0.f;

    const int KT = Kd / BK;
    for (int kt = 0; kt < KT; kt++) {
        const int cur = kt & 1;
        if (kt + 1 < KT) {
            const int k0 = (kt + 1) * BK;
            pa0 = *(const float4*)(A + (size_t)(rowBase + ar) * Kd + k0 + ac);
            pa1 = *(const float4*)(A + (size_t)(rowBase + ar + 64) * Kd + k0 + ac);
            if (TRB) {
                pb0 = *(const float4*)(B + (size_t)(colBase + tn) * Kd + k0 + tk);
                pb1 = *(const float4*)(B + (size_t)(colBase + tn + 64) * Kd + k0 + tk);
            } else {
                pb0 = *(const float4*)(B + (size_t)(k0 + br) * Nd + colBase + bc);
                pb1 = *(const float4*)(B + (size_t)(k0 + br + 8) * Nd + colBase + bc);
            }
        }
#pragma unroll
        for (int ks = 0; ks < 2; ks++) {
            const int kb = ks * 8;
            unsigned bhi[4][2], blo[4][2];
#pragma unroll
            for (int ni = 0; ni < 4; ni++) {
                float b0 = Bs[cur][kb + tig][wn + ni * 8 + grp];
                float b1 = Bs[cur][kb + tig + 4][wn + ni * 8 + grp];
                float lo0, lo1;
                bhi[ni][0] = tf32_split(b0, lo0);
                bhi[ni][1] = tf32_split(b1, lo1);
                blo[ni][0] = __float_as_uint(lo0);
                blo[ni][1] = __float_as_uint(lo1);
            }
#pragma unroll
            for (int mi = 0; mi < 4; mi++) {
                const int mb = wm + mi * 16 + grp;
                float a0 = As[cur][kb + tig][mb];
                float a1 = As[cur][kb + tig][mb + 8];
                float a2 = As[cur][kb + tig + 4][mb];
                float a3 = As[cur][kb + tig + 4][mb + 8];
                float la0, la1, la2, la3;
                unsigned h0 = tf32_split(a0, la0);
                unsigned h1 = tf32_split(a1, la1);
                unsigned h2 = tf32_split(a2, la2);
                unsigned h3 = tf32_split(a3, la3);
                unsigned l0 = __float_as_uint(la0);
                unsigned l1 = __float_as_uint(la1);
                unsigned l2 = __float_as_uint(la2);
                unsigned l3 = __float_as_uint(la3);
#pragma unroll
                for (int ni = 0; ni < 4; ni++) {
                    mma_tf32(acc[mi][ni], h0, h1, h2, h3, blo[ni][0], blo[ni][1]);
                    mma_tf32(acc[mi][ni], l0, l1, l2, l3, bhi[ni][0], bhi[ni][1]);
                    mma_tf32(acc[mi][ni], h0, h1, h2, h3, bhi[ni][0], bhi[ni][1]);
                }
            }
        }
        if (kt + 1 < KT) {
            const int nxt = cur ^ 1;
            As[nxt][ac + 0][ar] = pa0.x; As[nxt][ac + 1][ar] = pa0.y;
            As[nxt][ac + 2][ar] = pa0.z; As[nxt][ac + 3][ar] = pa0.w;
            As[nxt][ac + 0][ar + 64] = pa1.x; As[nxt][ac + 1][ar + 64] = pa1.y;
            As[nxt][ac + 2][ar + 64] = pa1.z; As[nxt][ac + 3][ar + 64] = pa1.w;
            if (TRB) {
                Bs[nxt][tk + 0][tn] = pb0.x; Bs[nxt][tk + 1][tn] = pb0.y;
                Bs[nxt][tk + 2][tn] = pb0.z; Bs[nxt][tk + 3][tn] = pb0.w;
                Bs[nxt][tk + 0][tn + 64] = pb1.x; Bs[nxt][tk + 1][tn + 64] = pb1.y;
                Bs[nxt][tk + 2][tn + 64] = pb1.z; Bs[nxt][tk + 3][tn + 64] = pb1.w;
            } else {
                *(float4*)&Bs[nxt][br][bc] = pb0;
                *(float4*)&Bs[nxt][br + 8][bc] = pb1;
            }
            __syncthreads();
        }
    }

#pragma unroll
    for (int mi = 0; mi < 4; mi++) {
        const int row = rowBase + wm + mi * 16 + grp;
#pragma unroll
        for (int ni = 0; ni < 4; ni++) {
            const int col = colBase + wn + ni * 8 + tig * 2;
            float c0 = acc[mi][ni][0], c1 = acc[mi][ni][1];
            float c2 = acc[mi][ni][2], c3 = acc[mi][ni][3];
            if (EPI == 2) {
                const float sr0 = sqb[row], sr8 = sqb[row + 8];
                const float sc0 = sqb[col], sc1 = sqb[col + 1];
                float2 v0, v1;
                v0.x = sr0 + sc0 - 2.f * c0;  v0.y = sr0 + sc1 - 2.f * c1;
                v1.x = sr8 + sc0 - 2.f * c2;  v1.y = sr8 + sc1 - 2.f * c3;
                *(float2*)&C[(size_t)row * Nd + col] = v0;
                *(float2*)&C[(size_t)(row + 8) * Nd + col] = v1;
                if (bx != by) {
                    C[(size_t)col * Nd + row]           = v0.x;
                    C[(size_t)col * Nd + row + 8]       = v1.x;
                    C[(size_t)(col + 1) * Nd + row]     = v0.y;
                    C[(size_t)(col + 1) * Nd + row + 8] = v1.y;
                }
            } else {
                float2 v0; v0.x = c0; v0.y = c1;
                float2 v1; v1.x = c2; v1.y = c3;
                *(float2*)&C[(size_t)row * Nd + col] = v0;
                *(float2*)&C[(size_t)(row + 8) * Nd + col] = v1;
            }
        }
    }
}

// ---------------------------------------------------------------------------
// Row squared norms
// ---------------------------------------------------------------------------
__global__ void sqnorm_kernel() {
    const int row = blockIdx.x, tid = threadIdx.x;
    __shared__ float sh[4];
    const float* xr = d_x + (size_t)row * HD;
    float4 v = *(const float4*)(xr + tid * 4);
    float s = v.x * v.x + v.y * v.y + v.z * v.z + v.w * v.w;
    const int lane = tid & 31, w = tid >> 5;
#pragma unroll
    for (int o = 16; o > 0; o >>= 1) s += __shfl_down_sync(0xffffffffu, s, o);
    if (lane == 0) sh[w] = s;
    __syncthreads();
    if (tid == 0) d_sq[row] = sh[0] + sh[1] + sh[2] + sh[3];
}

// ---------------------------------------------------------------------------
// Approx top-KC candidates per row from d2. Warp per row.
// ---------------------------------------------------------------------------
__global__ void topk_kernel() {
    const int w = threadIdx.x >> 5;
    const int lane = threadIdx.x & 31;
    const int row = blockIdx.x * 4 + w;
    const int b = row >> 11;
    const int i = row & (NI - 1);
    const float* drow = d_d2 + (size_t)b * NI * NI + (size_t)i * NI;

    float bd[KC]; int bix[KC];
#pragma unroll
    for (int k = 0; k < KC; k++) { bd[k] = 3.4e38f; bix[k] = 0x7fffffff; }

    for (int j0 = lane * 4; j0 < NI; j0 += 128) {
        float4 dv = *(const float4*)(drow + j0);
        float vs[4] = {dv.x, dv.y, dv.z, dv.w};
#pragma unroll
        for (int t = 0; t < 4; t++) {
            float v = vs[t];
            if (v < bd[KC - 1]) {
                bd[KC - 1] = v; bix[KC - 1] = j0 + t;
#pragma unroll
                for (int q = KC - 1; q > 0; q--) {
                    if (bd[q] < bd[q - 1]) {
                        float tf = bd[q]; bd[q] = bd[q - 1]; bd[q - 1] = tf;
                        int ti = bix[q]; bix[q] = bix[q - 1]; bix[q - 1] = ti;
                    }
                }
            }
        }
    }

    int* oc = d_cand + (size_t)row * KC;
    int cp = 0;
    float cv = bd[0]; int ci = bix[0];
#pragma unroll
    for (int k = 0; k < KC; k++) {
        float rv = cv; int ri = ci;
#pragma unroll
        for (int off = 16; off > 0; off >>= 1) {
            float ov = __shfl_xor_sync(0xffffffffu, rv, off);
            int   oj = __shfl_xor_sync(0xffffffffu, ri, off);
            if (ov < rv || (ov == rv && oj < ri)) { rv = ov; ri = oj; }
        }
        if (lane == 0) oc[k] = ri;
        if (cv == rv && ci == ri) {
            cp++;
            float nv = 3.4e38f; int ni2 = 0x7fffffff;
#pragma unroll
            for (int q = 1; q < KC; q++) if (cp == q) { nv = bd[q]; ni2 = bix[q]; }
            cv = nv; ci = ni2;
        }
    }
}

// ---------------------------------------------------------------------------
// Exact fp32 re-rank of the KC candidates -> true top-KN.
// ---------------------------------------------------------------------------
__global__ void rerank_kernel() {
    const int row = blockIdx.x;
    const int b = row >> 11;
    const int wid = threadIdx.x >> 5, lane = threadIdx.x & 31;
    __shared__ float sval[KC];
    __shared__ int   sidx[KC];

    if (wid < KC) {
        const int j = d_cand[(size_t)row * KC + wid];
        const float* xi = d_x + (size_t)row * HD;
        const float* xj = d_x + (size_t)(b * NI + j) * HD;
        float acc = 0.f;
#pragma unroll
        for (int t = 0; t < 4; t++) {
            float4 a = *(const float4*)(xi + (lane + t * 32) * 4);
            float4 c = *(const float4*)(xj + (lane + t * 32) * 4);
            acc += a.x * c.x + a.y * c.y + a.z * c.z + a.w * c.w;
        }
#pragma unroll
        for (int o = 16; o > 0; o >>= 1) acc += __shfl_down_sync(0xffffffffu, acc, o);
        if (lane == 0) {
            sval[wid] = d_sq[b * NI + j] - 2.f * acc;  // + sq_i (common) omitted
            sidx[wid] = j;
        }
    }
    __syncthreads();
    if (threadIdx.x == 0) {
        int* oi = d_idx + (size_t)row * KN;
        bool used[KC];
#pragma unroll
        for (int k = 0; k < KC; k++) used[k] = false;
#pragma unroll
        for (int k = 0; k < KN; k++) {
            float best = 3.5e38f; int bi = 0x7fffffff; int bp = 0;
#pragma unroll
            for (int t = 0; t < KC; t++) {
                if (!used[t]) {
                    float v = sval[t]; int ii = sidx[t];
                    if (v < best || (v == best && ii < bi)) { best = v; bi = ii; bp = t; }
                }
            }
            used[bp] = true;
            oi[k] = bi;
        }
    }
}

// ---------------------------------------------------------------------------
// EdgeConv: g[row,h] = max_k relu(P - Q + b_g + Q[nbr_k])
// ---------------------------------------------------------------------------
__global__ void edgeconv_kernel(const float* __restrict__ bgv) {
    const int row = blockIdx.x;
    const int b = row >> 11;
    const int tid = threadIdx.x;
    __shared__ int sj[KN];
    if (tid < KN) sj[tid] = d_idx[(size_t)row * KN + tid];
    __syncthreads();
    const int hh = tid * 4;
    float4 p  = *(const float4*)(d_P + (size_t)row * HD + hh);
    float4 q  = *(const float4*)(d_Q + (size_t)row * HD + hh);
    float4 bg = *(const float4*)(bgv + hh);
    float bx_ = p.x - q.x + bg.x;
    float by_ = p.y - q.y + bg.y;
    float bz_ = p.z - q.z + bg.z;
    float bw_ = p.w - q.w + bg.w;
    float mx = 0.f, my = 0.f, mz = 0.f, mw = 0.f;
    const float* Qb = d_Q + (size_t)b * NI * HD;
#pragma unroll
    for (int k = 0; k < KN; k++) {
        float4 qk = *(const float4*)(Qb + (size_t)sj[k] * HD + hh);
        mx = fmaxf(mx, bx_ + qk.x);
        my = fmaxf(my, by_ + qk.y);
        mz = fmaxf(mz, bz_ + qk.z);
        mw = fmaxf(mw, bw_ + qk.w);
    }
    float4 o; o.x = mx; o.y = my; o.z = mz; o.w = mw;
    *(float4*)(d_g + (size_t)row * HD + hh) = o;
}

__device__ __forceinline__ float blockReduceSum(float v, float* sh) {
    int lane = threadIdx.x & 31, w = threadIdx.x >> 5;
#pragma unroll
    for (int o = 16; o > 0; o >>= 1) v += __shfl_down_sync(0xffffffffu, v, o);
    if (lane == 0) sh[w] = v;
    __syncthreads();
    int nw = blockDim.x >> 5;
    v = (threadIdx.x < nw) ? sh[threadIdx.x] : 0.f;
    if (w == 0)
#pragma unroll
        for (int o = 16; o > 0; o >>= 1) v += __shfl_down_sync(0xffffffffu, v, o);
    return v;
}

// ---------------------------------------------------------------------------
// Gated attention score -> A_raw (adds biases since gemm_tc no longer does)
// ---------------------------------------------------------------------------
__global__ void gate_kernel(const float* __restrict__ ba, const float* __restrict__ bb,
                            const float* __restrict__ Wc, const float* __restrict__ bc,
                            float* __restrict__ out) {
    const int row = blockIdx.x, tid = threadIdx.x;
    __shared__ float sh[32];
    const float* ap = d_Ap + (size_t)row * DA;
    const float* bp = d_Bp + (size_t)row * DA;
    float s = 0.f;
    for (int dd = tid; dd < DA; dd += 128) {
        float av = tanhf(ap[dd] + ba[dd]);
        float bv = bp[dd] + bb[dd];
        bv = 1.f / (1.f + expf(-bv));
        s += av * bv * Wc[dd];
    }
    s = blockReduceSum(s, sh);
    if (tid == 0) {
        float v = s + bc[0];
        d_Ar[row] = v;
        out[2 * NB * NC + row] = v;
    }
}

// ---------------------------------------------------------------------------
// Per-bag softmax stats; zero d_M.
// ---------------------------------------------------------------------------
__global__ void attn_stats_kernel() {
    const int b = blockIdx.x, tid = threadIdx.x;
    __shared__ float red[512];
    float* Ar = d_Ar + (size_t)b * NI;

    float mx = -3.4e38f;
    for (int n = tid; n < NI; n += 512) mx = fmaxf(mx, Ar[n]);
    red[tid] = mx; __syncthreads();
    for (int s = 256; s > 0; s >>= 1) { if (tid < s) red[tid] = fmaxf(red[tid], red[tid + s]); __syncthreads(); }
    mx = red[0];
    __syncthreads();

    float sum = 0.f;
    for (int n = tid; n < NI; n += 512) sum += expf(Ar[n] - mx);
    red[tid] = sum; __syncthreads();
    for (int s = 256; s > 0; s >>= 1) { if (tid < s) red[tid] += red[tid + s]; __syncthreads(); }
    const float inv = 1.f / red[0];
    __syncthreads();

    for (int n = tid; n < NI; n += 512) Ar[n] = expf(Ar[n] - mx) * inv;
    d_M[b * HD + tid] = 0.f;
}

// ---------------------------------------------------------------------------
// Chunked weighted pooling with atomics
// ---------------------------------------------------------------------------
__global__ void pool_acc_kernel() {
    const int b = blockIdx.x, ch = blockIdx.y, tid = threadIdx.x;
    const float* w  = d_Ar + (size_t)b * NI + ch * 128;
    const float* gb = d_g + ((size_t)b * NI + (size_t)ch * 128) * HD;
    __shared__ float ws[128];
    if (tid < 128) ws[tid] = w[tid];
    __syncthreads();
    const int c0 = tid, c1 = tid + 256;
    float a0 = 0.f, a1 = 0.f;
    for (int n = 0; n < 128; n++) {
        const float wn = ws[n];
        a0 = fmaf(wn, gb[(size_t)n * HD + c0], a0);
        a1 = fmaf(wn, gb[(size_t)n * HD + c1], a1);
    }
    atomicAdd(&d_M[b * HD + c0], a0);
    atomicAdd(&d_M[b * HD + c1], a1);
}

// ---------------------------------------------------------------------------
// Classifier head + Y_prob
// ---------------------------------------------------------------------------
__global__ void head_kernel(const float* __restrict__ Wcls, const float* __restrict__ bcls,
                            float* __restrict__ out) {
    const int b = blockIdx.x, tid = threadIdx.x;
    __shared__ float sh[32];
    float s0 = 0.f, s1 = 0.f;
    for (int hh = tid; hh < HD; hh += 128) {
        float m = d_M[b * HD + hh];
        s0 = fmaf(m, Wcls[hh * NC + 0], s0);
        s1 = fmaf(m, Wcls[hh * NC + 1], s1);
    }
    s0 = blockReduceSum(s0, sh);
    __syncthreads();
    s1 = blockReduceSum(s1, sh);
    if (tid == 0) {
        float l0 = s0 + bcls[0], l1 = s1 + bcls[1];
        out[b * NC + 0] = l0;
        out[b * NC + 1] = l1;
        float mx = fmaxf(l0, l1);
        float e0 = expf(l0 - mx), e1 = expf(l1 - mx);
        float inv = 1.f / (e0 + e1);
        out[NB * NC + b * NC + 0] = e0 * inv;
        out[NB * NC + b * NC + 1] = e1 * inv;
    }
}

// ---------------------------------------------------------------------------
extern "C" void kernel_launch(void* const* d_in, const int* in_sizes, int n_in,
                              void* d_out, int out_size) {
    const float* h     = (const float*)d_in[0];
    const float* W_fc  = (const float*)d_in[1];
    const float* b_fc  = (const float*)d_in[2];
    const float* W_g   = (const float*)d_in[3];
    const float* b_g   = (const float*)d_in[4];
    const float* W_a   = (const float*)d_in[5];
    const float* b_a   = (const float*)d_in[6];
    const float* W_b   = (const float*)d_in[7];
    const float* b_b   = (const float*)d_in[8];
    const float* W_c   = (const float*)d_in[9];
    const float* b_c   = (const float*)d_in[10];
    const float* W_cls = (const float*)d_in[11];
    const float* b_cls = (const float*)d_in[12];
    float* out = (float*)d_out;

    void *px, *pP, *pQ, *pg, *pAp, *pBp, *pd2;
    cudaGetSymbolAddress(&px, d_x);
    cudaGetSymbolAddress(&pP, d_P);
    cudaGetSymbolAddress(&pQ, d_Q);
    cudaGetSymbolAddress(&pg, d_g);
    cudaGetSymbolAddress(&pAp, d_Ap);
    cudaGetSymbolAddress(&pBp, d_Bp);
    cudaGetSymbolAddress(&pd2, d_d2);
    float* x  = (float*)px;
    float* P  = (float*)pP;
    float* Q  = (float*)pQ;
    float* g  = (float*)pg;
    float* Ap = (float*)pAp;
    float* Bp = (float*)pBp;
    float* d2 = (float*)pd2;

    // 1. x = relu(h @ W_fc + b_fc)  — fp32 FFMA (kNN-critical path)
    gemm_f32_relu<<<dim3(HD / FBN, MROWS / FBM), 256>>>(h, W_fc, b_fc, x, MROWS, DIM, HD);
    // 2. squared norms
    sqnorm_kernel<<<MROWS, 128>>>();
    // 3. per-bag Gram -> approx d2 (rna-tf32-3x, upper blocks + mirror)
    gemm_tc<2, 1><<<dim3(NI / BN, NI / BM, NB), 256>>>(x, x, d2, NI, HD, NI);
    // 4a. approx top-KC candidates
    topk_kernel<<<MROWS / 4, 128>>>();
    // 4b. exact fp32 re-rank -> top-KN
    rerank_kernel<<<MROWS, KC * 32>>>();
    // 5/6. EdgeConv decomposition: P = x@Wg_top, Q = x@Wg_bot (tf32-3x, smooth)
    gemm_tc<0, 0><<<dim3(HD / BN, MROWS / BM), 256>>>(x, W_g, P, MROWS, HD, HD);
    gemm_tc<0, 0><<<dim3(HD / BN, MROWS / BM), 256>>>(x, W_g + (size_t)HD * HD, Q, MROWS, HD, HD);
    // 7. edgeconv gather + max (b_g added here)
    edgeconv_kernel<<<MROWS, 128>>>(b_g);
    // 8/9. attention pre-projections (tf32-3x, smooth; biases added in gate)
    gemm_tc<0, 0><<<dim3(DA / BN, MROWS / BM), 256>>>(g, W_a, Ap, MROWS, HD, DA);
    gemm_tc<0, 0><<<dim3(DA / BN, MROWS / BM), 256>>>(g, W_b, Bp, MROWS, HD, DA);
    // 10. gated attention score -> A_raw
    gate_kernel<<<MROWS, 128>>>(b_a, b_b, W_c, b_c, out);
    // 11. softmax stats + zero M
    attn_stats_kernel<<<NB, 512>>>();
    // 12. chunked weighted pooling
    pool_acc_kernel<<<dim3(NB, 16), 256>>>();
    // 13. classifier head + Y_prob
    head_kernel<<<NB, 128>>>(W_cls, b_cls, out);
}

// round 10
// speedup vs baseline: 5.6956x; 1.2804x over previous
#include <cuda_runtime.h>
#include <cuda_bf16.h>
#include <math.h>
#include <cstdint>

constexpr int NB  = 8;
constexpr int NI  = 2048;
constexpr int DIM = 1024;
constexpr int HD  = 512;
constexpr int DA  = 256;
constexpr int KN  = 5;
constexpr int KC  = 9;      // candidates for exact re-rank
constexpr int NC  = 2;
constexpr int MROWS = NB * NI;   // 16384

// Scratch (static device globals)
__device__ float d_x [MROWS * HD];
__device__ float d_sq[MROWS];
__device__ float d_d2[(size_t)NB * NI * NI];   // 128 MB
__device__ int   d_cand[MROWS * KC];
__device__ int   d_idx[MROWS * KN];
__device__ float d_P [MROWS * HD];
__device__ float d_Q [MROWS * HD];
__device__ float d_g [MROWS * HD];
__device__ float d_Ap[MROWS * DA];
__device__ float d_Bp[MROWS * DA];
__device__ float d_Ar[MROWS];
__device__ float d_M [NB * HD];

// ===========================================================================
// PART 1: fp32 FFMA GEMM (exact) — fc layer only (kNN-critical x).
// 128x128x8 tile, 256 threads, 8x8/thread, double-buffered, relu+bias.
// ===========================================================================
constexpr int FBM = 128, FBN = 128, FBK = 8;

__global__ __launch_bounds__(256, 2)
void gemm_f32_relu(const float* __restrict__ A, const float* __restrict__ Bm,
                   const float* __restrict__ bias, float* __restrict__ Cm,
                   int M, int Kd, int Nd) {
    __shared__ float As[2][FBK][FBM];
    __shared__ float Bs[2][FBK][FBN];
    const int tid = threadIdx.x;
    const int tx = tid & 15, ty = tid >> 4;
    const int rowBase = blockIdx.y * FBM;
    const int colBase = blockIdx.x * FBN;
    const int arow = tid >> 1, acol = (tid & 1) * 4;
    const int brow = tid >> 5, bcol = (tid & 31) * 4;

    float4 aR = *(const float4*)(A + (size_t)(rowBase + arow) * Kd + acol);
    float4 bR = *(const float4*)(Bm + (size_t)brow * Nd + colBase + bcol);
    As[0][acol + 0][arow] = aR.x; As[0][acol + 1][arow] = aR.y;
    As[0][acol + 2][arow] = aR.z; As[0][acol + 3][arow] = aR.w;
    *(float4*)&Bs[0][brow][bcol] = bR;
    __syncthreads();

    float acc[8][8];
#pragma unroll
    for (int m = 0; m < 8; m++)
#pragma unroll
        for (int n = 0; n < 8; n++) acc[m][n] = 0.f;

    const int KT = Kd / FBK;
    for (int kt = 0; kt < KT; kt++) {
        const int cur = kt & 1;
        if (kt + 1 < KT) {
            const int k0 = (kt + 1) * FBK;
            aR = *(const float4*)(A + (size_t)(rowBase + arow) * Kd + k0 + acol);
            bR = *(const float4*)(Bm + (size_t)(k0 + brow) * Nd + colBase + bcol);
        }
#pragma unroll
        for (int kk = 0; kk < FBK; kk++) {
            float4 a0 = *(const float4*)&As[cur][kk][ty * 4];
            float4 a1 = *(const float4*)&As[cur][kk][64 + ty * 4];
            float4 b0 = *(const float4*)&Bs[cur][kk][tx * 4];
            float4 b1 = *(const float4*)&Bs[cur][kk][64 + tx * 4];
            float av[8] = {a0.x, a0.y, a0.z, a0.w, a1.x, a1.y, a1.z, a1.w};
            float bv[8] = {b0.x, b0.y, b0.z, b0.w, b1.x, b1.y, b1.z, b1.w};
#pragma unroll
            for (int m = 0; m < 8; m++)
#pragma unroll
                for (int n = 0; n < 8; n++)
                    acc[m][n] = fmaf(av[m], bv[n], acc[m][n]);
        }
        if (kt + 1 < KT) {
            const int nxt = cur ^ 1;
            As[nxt][acol + 0][arow] = aR.x; As[nxt][acol + 1][arow] = aR.y;
            As[nxt][acol + 2][arow] = aR.z; As[nxt][acol + 3][arow] = aR.w;
            *(float4*)&Bs[nxt][brow][bcol] = bR;
            __syncthreads();
        }
    }

#pragma unroll
    for (int m = 0; m < 8; m++) {
        const int r = rowBase + ((m < 4) ? (ty * 4 + m) : (64 + ty * 4 + (m - 4)));
        const int c0 = colBase + tx * 4;
        const int c1 = colBase + 64 + tx * 4;
        float4 t0 = *(const float4*)&bias[c0];
        float4 t1 = *(const float4*)&bias[c1];
        float4 v0, v1;
        v0.x = fmaxf(acc[m][0] + t0.x, 0.f); v0.y = fmaxf(acc[m][1] + t0.y, 0.f);
        v0.z = fmaxf(acc[m][2] + t0.z, 0.f); v0.w = fmaxf(acc[m][3] + t0.w, 0.f);
        v1.x = fmaxf(acc[m][4] + t1.x, 0.f); v1.y = fmaxf(acc[m][5] + t1.y, 0.f);
        v1.z = fmaxf(acc[m][6] + t1.z, 0.f); v1.w = fmaxf(acc[m][7] + t1.w, 0.f);
        *(float4*)&Cm[(size_t)r * Nd + c0] = v0;
        *(float4*)&Cm[(size_t)r * Nd + c1] = v1;
    }
}

// ===========================================================================
// PART 2: bf16-3x GEMM via mma.sync.m16n8k16 (base sm_103-legal).
// Split staged ONCE into hi/lo bf16 smem tiles; inner loop is pure LDS+MMA.
// D += Ahi*Bhi + Ahi*Blo + Alo*Bhi  (lo*lo ~2^-16 dropped).
// EPI: 0 = plain A@B, 2 = per-bag Gram -> d2 + symmetric mirror.
// TRB: B row-major [Nd x Kd] (use B^T).
// ===========================================================================
constexpr int XBM = 128, XBN = 128, XBK = 16;
constexpr int LDW = 136;              // padded u32 row (bank-perfect frags)
constexpr int ARR = 8 * LDW;          // u32 per array

__device__ __forceinline__ uint32_t pack_hi(float a, float b, float& la, float& lb) {
    __nv_bfloat16 ha = __float2bfloat16_rn(a);
    __nv_bfloat16 hb = __float2bfloat16_rn(b);
    la = a - __bfloat162float(ha);
    lb = b - __bfloat162float(hb);
    return ((uint32_t)__bfloat16_as_ushort(hb) << 16) | __bfloat16_as_ushort(ha);
}
__device__ __forceinline__ uint32_t pack_lo(float la, float lb) {
    __nv_bfloat162 t = __floats2bfloat162_rn(la, lb);
    return *(uint32_t*)&t;
}
__device__ __forceinline__ void mma_bf16(float* c, uint32_t a0, uint32_t a1,
                                         uint32_t a2, uint32_t a3,
                                         uint32_t b0, uint32_t b1) {
    asm volatile(
        "mma.sync.aligned.m16n8k16.row.col.f32.bf16.bf16.f32 "
        "{%0,%1,%2,%3}, {%4,%5,%6,%7}, {%8,%9}, {%0,%1,%2,%3};\n"
        : "+f"(c[0]), "+f"(c[1]), "+f"(c[2]), "+f"(c[3])
        : "r"(a0), "r"(a1), "r"(a2), "r"(a3), "r"(b0), "r"(b1));
}

template <int EPI, int TRB>
__global__ __launch_bounds__(256, 2)
void gemm_bf(const float* __restrict__ Aall, const float* __restrict__ Ball,
             float* __restrict__ Call, int M, int Kd, int Nd) {
    const int bx = blockIdx.x, by = blockIdx.y;
    const float* A = Aall;
    const float* B = Ball;
    float* C = Call;
    const float* sqb = nullptr;
    if (EPI == 2) {
        if (by > bx) return;
        const int bag = blockIdx.z;
        A = Aall + (size_t)bag * NI * HD;
        B = A;
        C = Call + (size_t)bag * NI * NI;
        sqb = d_sq + bag * NI;
    }
    const int rowBase = by * XBM, colBase = bx * XBN;

    // [buf][Ahi=0, Alo=1, Bhi=2, Blo=3][8*LDW]
    __shared__ uint32_t S[2][4][ARR];

    const int tid = threadIdx.x;
    const int lane = tid & 31;
    const int grp = lane >> 2;        // 0..7
    const int tig = lane & 3;         // 0..3
    const int warpId = tid >> 5;
    const int wm = (warpId & 1) * 64;
    const int wn = (warpId >> 1) * 32;

    // staging maps
    const int sa_row = tid >> 3;      // 0..31 (x4 passes)
    const int sa_k2  = tid & 7;       // 0..7
    const int sb_k2  = tid >> 5;      // 0..7 (non-TRB B)
    const int sb_n   = (tid & 31) * 4;

    float2 pa[4];
    float2 pb[4];                      // TRB B
    float4 pw0, pw1;                   // non-TRB B

    // ---- gmem load helper (into regs) ----
    auto gload = [&](int k0) {
#pragma unroll
        for (int p = 0; p < 4; p++)
            pa[p] = *(const float2*)(A + (size_t)(rowBase + p * 32 + sa_row) * Kd + k0 + sa_k2 * 2);
        if (TRB) {
#pragma unroll
            for (int p = 0; p < 4; p++)
                pb[p] = *(const float2*)(B + (size_t)(colBase + p * 32 + sa_row) * Kd + k0 + sa_k2 * 2);
        } else {
            const int k = k0 + sb_k2 * 2;
            pw0 = *(const float4*)(B + (size_t)k * Nd + colBase + sb_n);
            pw1 = *(const float4*)(B + (size_t)(k + 1) * Nd + colBase + sb_n);
        }
    };
    // ---- smem store helper ----
    auto sstore = [&](int buf) {
#pragma unroll
        for (int p = 0; p < 4; p++) {
            const int row = p * 32 + sa_row;
            float la, lb;
            uint32_t h = pack_hi(pa[p].x, pa[p].y, la, lb);
            S[buf][0][sa_k2 * LDW + row] = h;
            S[buf][1][sa_k2 * LDW + row] = pack_lo(la, lb);
        }
        if (TRB) {
#pragma unroll
            for (int p = 0; p < 4; p++) {
                const int n = p * 32 + sa_row;
                float la, lb;
                uint32_t h = pack_hi(pb[p].x, pb[p].y, la, lb);
                S[buf][2][sa_k2 * LDW + n] = h;
                S[buf][3][sa_k2 * LDW + n] = pack_lo(la, lb);
            }
        } else {
            float l0, l1, l2, l3, l4, l5, l6, l7;
            uint32_t h0 = pack_hi(pw0.x, pw1.x, l0, l1);
            uint32_t h1 = pack_hi(pw0.y, pw1.y, l2, l3);
            uint32_t h2 = pack_hi(pw0.z, pw1.z, l4, l5);
            uint32_t h3 = pack_hi(pw0.w, pw1.w, l6, l7);
            *(uint4*)&S[buf][2][sb_k2 * LDW + sb_n] = make_uint4(h0, h1, h2, h3);
            *(uint4*)&S[buf][3][sb_k2 * LDW + sb_n] =
                make_uint4(pack_lo(l0, l1), pack_lo(l2, l3), pack_lo(l4, l5), pack_lo(l6, l7));
        }
    };

    gload(0);
    sstore(0);
    __syncthreads();

    float acc[4][4][4];
#pragma unroll
    for (int mi = 0; mi < 4; mi++)
#pragma unroll
        for (int ni = 0; ni < 4; ni++)
#pragma unroll
            for (int q = 0; q < 4; q++) acc[mi][ni][q] = 0.f;

    const int KT = Kd / XBK;
    for (int kt = 0; kt < KT; kt++) {
        const int cur = kt & 1;
        if (kt + 1 < KT) gload((kt + 1) * XBK);

        // B fragments (hi/lo) for all ni
        uint32_t bhi[4][2], blo[4][2];
#pragma unroll
        for (int ni = 0; ni < 4; ni++) {
            const int n = wn + ni * 8 + grp;
            bhi[ni][0] = S[cur][2][tig * LDW + n];
            bhi[ni][1] = S[cur][2][(tig + 4) * LDW + n];
            blo[ni][0] = S[cur][3][tig * LDW + n];
            blo[ni][1] = S[cur][3][(tig + 4) * LDW + n];
        }
#pragma unroll
        for (int mi = 0; mi < 4; mi++) {
            const int r = wm + mi * 16 + grp;
            uint32_t ah0 = S[cur][0][tig * LDW + r];
            uint32_t ah1 = S[cur][0][tig * LDW + r + 8];
            uint32_t ah2 = S[cur][0][(tig + 4) * LDW + r];
            uint32_t ah3 = S[cur][0][(tig + 4) * LDW + r + 8];
            uint32_t al0 = S[cur][1][tig * LDW + r];
            uint32_t al1 = S[cur][1][tig * LDW + r + 8];
            uint32_t al2 = S[cur][1][(tig + 4) * LDW + r];
            uint32_t al3 = S[cur][1][(tig + 4) * LDW + r + 8];
#pragma unroll
            for (int ni = 0; ni < 4; ni++) {
                mma_bf16(acc[mi][ni], ah0, ah1, ah2, ah3, bhi[ni][0], bhi[ni][1]);
                mma_bf16(acc[mi][ni], ah0, ah1, ah2, ah3, blo[ni][0], blo[ni][1]);
                mma_bf16(acc[mi][ni], al0, al1, al2, al3, bhi[ni][0], bhi[ni][1]);
            }
        }
        if (kt + 1 < KT) {
            sstore(cur ^ 1);
            __syncthreads();
        }
    }

    // ---- epilogue ----
#pragma unroll
    for (int mi = 0; mi < 4; mi++) {
        const int row = rowBase + wm + mi * 16 + grp;
#pragma unroll
        for (int ni = 0; ni < 4; ni++) {
            const int col = colBase + wn + ni * 8 + tig * 2;
            float c0 = acc[mi][ni][0], c1 = acc[mi][ni][1];
            float c2 = acc[mi][ni][2], c3 = acc[mi][ni][3];
            if (EPI == 2) {
                const float sr0 = sqb[row], sr8 = sqb[row + 8];
                const float sc0 = sqb[col], sc1 = sqb[col + 1];
                float2 v0, v1;
                v0.x = sr0 + sc0 - 2.f * c0;  v0.y = sr0 + sc1 - 2.f * c1;
                v1.x = sr8 + sc0 - 2.f * c2;  v1.y = sr8 + sc1 - 2.f * c3;
                *(float2*)&C[(size_t)row * Nd + col] = v0;
                *(float2*)&C[(size_t)(row + 8) * Nd + col] = v1;
                if (bx != by) {
                    C[(size_t)col * Nd + row]           = v0.x;
                    C[(size_t)col * Nd + row + 8]       = v1.x;
                    C[(size_t)(col + 1) * Nd + row]     = v0.y;
                    C[(size_t)(col + 1) * Nd + row + 8] = v1.y;
                }
            } else {
                float2 v0; v0.x = c0; v0.y = c1;
                float2 v1; v1.x = c2; v1.y = c3;
                *(float2*)&C[(size_t)row * Nd + col] = v0;
                *(float2*)&C[(size_t)(row + 8) * Nd + col] = v1;
            }
        }
    }
}

// ---------------------------------------------------------------------------
// Row squared norms
// ---------------------------------------------------------------------------
__global__ void sqnorm_kernel() {
    const int row = blockIdx.x, tid = threadIdx.x;
    __shared__ float sh[4];
    const float* xr = d_x + (size_t)row * HD;
    float4 v = *(const float4*)(xr + tid * 4);
    float s = v.x * v.x + v.y * v.y + v.z * v.z + v.w * v.w;
    const int lane = tid & 31, w = tid >> 5;
#pragma unroll
    for (int o = 16; o > 0; o >>= 1) s += __shfl_down_sync(0xffffffffu, s, o);
    if (lane == 0) sh[w] = s;
    __syncthreads();
    if (tid == 0) d_sq[row] = sh[0] + sh[1] + sh[2] + sh[3];
}

// ---------------------------------------------------------------------------
// Approx top-KC candidates per row. Warp per row.
// ---------------------------------------------------------------------------
__global__ void topk_kernel() {
    const int w = threadIdx.x >> 5;
    const int lane = threadIdx.x & 31;
    const int row = blockIdx.x * 4 + w;
    const int b = row >> 11;
    const int i = row & (NI - 1);
    const float* drow = d_d2 + (size_t)b * NI * NI + (size_t)i * NI;

    float bd[KC]; int bix[KC];
#pragma unroll
    for (int k = 0; k < KC; k++) { bd[k] = 3.4e38f; bix[k] = 0x7fffffff; }

    for (int j0 = lane * 4; j0 < NI; j0 += 128) {
        float4 dv = *(const float4*)(drow + j0);
        float vs[4] = {dv.x, dv.y, dv.z, dv.w};
#pragma unroll
        for (int t = 0; t < 4; t++) {
            float v = vs[t];
            if (v < bd[KC - 1]) {
                bd[KC - 1] = v; bix[KC - 1] = j0 + t;
#pragma unroll
                for (int q = KC - 1; q > 0; q--) {
                    if (bd[q] < bd[q - 1]) {
                        float tf = bd[q]; bd[q] = bd[q - 1]; bd[q - 1] = tf;
                        int ti = bix[q]; bix[q] = bix[q - 1]; bix[q - 1] = ti;
                    }
                }
            }
        }
    }

    int* oc = d_cand + (size_t)row * KC;
    int cp = 0;
    float cv = bd[0]; int ci = bix[0];
#pragma unroll
    for (int k = 0; k < KC; k++) {
        float rv = cv; int ri = ci;
#pragma unroll
        for (int off = 16; off > 0; off >>= 1) {
            float ov = __shfl_xor_sync(0xffffffffu, rv, off);
            int   oj = __shfl_xor_sync(0xffffffffu, ri, off);
            if (ov < rv || (ov == rv && oj < ri)) { rv = ov; ri = oj; }
        }
        if (lane == 0) oc[k] = ri;
        if (cv == rv && ci == ri) {
            cp++;
            float nv = 3.4e38f; int ni2 = 0x7fffffff;
#pragma unroll
            for (int q = 1; q < KC; q++) if (cp == q) { nv = bd[q]; ni2 = bix[q]; }
            cv = nv; ci = ni2;
        }
    }
}

// ---------------------------------------------------------------------------
// Exact fp32 re-rank of KC candidates -> true top-KN.
// ---------------------------------------------------------------------------
__global__ void rerank_kernel() {
    const int row = blockIdx.x;
    const int b = row >> 11;
    const int wid = threadIdx.x >> 5, lane = threadIdx.x & 31;
    __shared__ float sval[KC];
    __shared__ int   sidx[KC];

    if (wid < KC) {
        const int j = d_cand[(size_t)row * KC + wid];
        const float* xi = d_x + (size_t)row * HD;
        const float* xj = d_x + (size_t)(b * NI + j) * HD;
        float acc = 0.f;
#pragma unroll
        for (int t = 0; t < 4; t++) {
            float4 a = *(const float4*)(xi + (lane + t * 32) * 4);
            float4 c = *(const float4*)(xj + (lane + t * 32) * 4);
            acc += a.x * c.x + a.y * c.y + a.z * c.z + a.w * c.w;
        }
#pragma unroll
        for (int o = 16; o > 0; o >>= 1) acc += __shfl_down_sync(0xffffffffu, acc, o);
        if (lane == 0) {
            sval[wid] = d_sq[b * NI + j] - 2.f * acc;
            sidx[wid] = j;
        }
    }
    __syncthreads();
    if (threadIdx.x == 0) {
        int* oi = d_idx + (size_t)row * KN;
        bool used[KC];
#pragma unroll
        for (int k = 0; k < KC; k++) used[k] = false;
#pragma unroll
        for (int k = 0; k < KN; k++) {
            float best = 3.5e38f; int bi = 0x7fffffff; int bp = 0;
#pragma unroll
            for (int t = 0; t < KC; t++) {
                if (!used[t]) {
                    float v = sval[t]; int ii = sidx[t];
                    if (v < best || (v == best && ii < bi)) { best = v; bi = ii; bp = t; }
                }
            }
            used[bp] = true;
            oi[k] = bi;
        }
    }
}

// ---------------------------------------------------------------------------
// EdgeConv: g[row,h] = max_k relu(P - Q + b_g + Q[nbr_k])
// ---------------------------------------------------------------------------
__global__ void edgeconv_kernel(const float* __restrict__ bgv) {
    const int row = blockIdx.x;
    const int b = row >> 11;
    const int tid = threadIdx.x;
    __shared__ int sj[KN];
    if (tid < KN) sj[tid] = d_idx[(size_t)row * KN + tid];
    __syncthreads();
    const int hh = tid * 4;
    float4 p  = *(const float4*)(d_P + (size_t)row * HD + hh);
    float4 q  = *(const float4*)(d_Q + (size_t)row * HD + hh);
    float4 bg = *(const float4*)(bgv + hh);
    float bx_ = p.x - q.x + bg.x;
    float by_ = p.y - q.y + bg.y;
    float bz_ = p.z - q.z + bg.z;
    float bw_ = p.w - q.w + bg.w;
    float mx = 0.f, my = 0.f, mz = 0.f, mw = 0.f;
    const float* Qb = d_Q + (size_t)b * NI * HD;
#pragma unroll
    for (int k = 0; k < KN; k++) {
        float4 qk = *(const float4*)(Qb + (size_t)sj[k] * HD + hh);
        mx = fmaxf(mx, bx_ + qk.x);
        my = fmaxf(my, by_ + qk.y);
        mz = fmaxf(mz, bz_ + qk.z);
        mw = fmaxf(mw, bw_ + qk.w);
    }
    float4 o; o.x = mx; o.y = my; o.z = mz; o.w = mw;
    *(float4*)(d_g + (size_t)row * HD + hh) = o;
}

__device__ __forceinline__ float blockReduceSum(float v, float* sh) {
    int lane = threadIdx.x & 31, w = threadIdx.x >> 5;
#pragma unroll
    for (int o = 16; o > 0; o >>= 1) v += __shfl_down_sync(0xffffffffu, v, o);
    if (lane == 0) sh[w] = v;
    __syncthreads();
    int nw = blockDim.x >> 5;
    v = (threadIdx.x < nw) ? sh[threadIdx.x] : 0.f;
    if (w == 0)
#pragma unroll
        for (int o = 16; o > 0; o >>= 1) v += __shfl_down_sync(0xffffffffu, v, o);
    return v;
}

// ---------------------------------------------------------------------------
// Gated attention score -> A_raw
// ---------------------------------------------------------------------------
__global__ void gate_kernel(const float* __restrict__ ba, const float* __restrict__ bb,
                            const float* __restrict__ Wc, const float* __restrict__ bc,
                            float* __restrict__ out) {
    const int row = blockIdx.x, tid = threadIdx.x;
    __shared__ float sh[32];
    const float* ap = d_Ap + (size_t)row * DA;
    const float* bp = d_Bp + (size_t)row * DA;
    float s = 0.f;
    for (int dd = tid; dd < DA; dd += 128) {
        float av = tanhf(ap[dd] + ba[dd]);
        float bv = bp[dd] + bb[dd];
        bv = 1.f / (1.f + expf(-bv));
        s += av * bv * Wc[dd];
    }
    s = blockReduceSum(s, sh);
    if (tid == 0) {
        float v = s + bc[0];
        d_Ar[row] = v;
        out[2 * NB * NC + row] = v;
    }
}

// ---------------------------------------------------------------------------
// Per-bag softmax stats; zero d_M.
// ---------------------------------------------------------------------------
__global__ void attn_stats_kernel() {
    const int b = blockIdx.x, tid = threadIdx.x;
    __shared__ float red[512];
    float* Ar = d_Ar + (size_t)b * NI;

    float mx = -3.4e38f;
    for (int n = tid; n < NI; n += 512) mx = fmaxf(mx, Ar[n]);
    red[tid] = mx; __syncthreads();
    for (int s = 256; s > 0; s >>= 1) { if (tid < s) red[tid] = fmaxf(red[tid], red[tid + s]); __syncthreads(); }
    mx = red[0];
    __syncthreads();

    float sum = 0.f;
    for (int n = tid; n < NI; n += 512) sum += expf(Ar[n] - mx);
    red[tid] = sum; __syncthreads();
    for (int s = 256; s > 0; s >>= 1) { if (tid < s) red[tid] += red[tid + s]; __syncthreads(); }
    const float inv = 1.f / red[0];
    __syncthreads();

    for (int n = tid; n < NI; n += 512) Ar[n] = expf(Ar[n] - mx) * inv;
    d_M[b * HD + tid] = 0.f;
}

// ---------------------------------------------------------------------------
// Chunked weighted pooling with atomics
// ---------------------------------------------------------------------------
__global__ void pool_acc_kernel() {
    const int b = blockIdx.x, ch = blockIdx.y, tid = threadIdx.x;
    const float* w  = d_Ar + (size_t)b * NI + ch * 128;
    const float* gb = d_g + ((size_t)b * NI + (size_t)ch * 128) * HD;
    __shared__ float ws[128];
    if (tid < 128) ws[tid] = w[tid];
    __syncthreads();
    const int c0 = tid, c1 = tid + 256;
    float a0 = 0.f, a1 = 0.f;
    for (int n = 0; n < 128; n++) {
        const float wn = ws[n];
        a0 = fmaf(wn, gb[(size_t)n * HD + c0], a0);
        a1 = fmaf(wn, gb[(size_t)n * HD + c1], a1);
    }
    atomicAdd(&d_M[b * HD + c0], a0);
    atomicAdd(&d_M[b * HD + c1], a1);
}

// ---------------------------------------------------------------------------
// Classifier head + Y_prob
// ---------------------------------------------------------------------------
__global__ void head_kernel(const float* __restrict__ Wcls, const float* __restrict__ bcls,
                            float* __restrict__ out) {
    const int b = blockIdx.x, tid = threadIdx.x;
    __shared__ float sh[32];
    float s0 = 0.f, s1 = 0.f;
    for (int hh = tid; hh < HD; hh += 128) {
        float m = d_M[b * HD + hh];
        s0 = fmaf(m, Wcls[hh * NC + 0], s0);
        s1 = fmaf(m, Wcls[hh * NC + 1], s1);
    }
    s0 = blockReduceSum(s0, sh);
    __syncthreads();
    s1 = blockReduceSum(s1, sh);
    if (tid == 0) {
        float l0 = s0 + bcls[0], l1 = s1 + bcls[1];
        out[b * NC + 0] = l0;
        out[b * NC + 1] = l1;
        float mx = fmaxf(l0, l1);
        float e0 = expf(l0 - mx), e1 = expf(l1 - mx);
        float inv = 1.f / (e0 + e1);
        out[NB * NC + b * NC + 0] = e0 * inv;
        out[NB * NC + b * NC + 1] = e1 * inv;
    }
}

// ---------------------------------------------------------------------------
extern "C" void kernel_launch(void* const* d_in, const int* in_sizes, int n_in,
                              void* d_out, int out_size) {
    const float* h     = (const float*)d_in[0];
    const float* W_fc  = (const float*)d_in[1];
    const float* b_fc  = (const float*)d_in[2];
    const float* W_g   = (const float*)d_in[3];
    const float* b_g   = (const float*)d_in[4];
    const float* W_a   = (const float*)d_in[5];
    const float* b_a   = (const float*)d_in[6];
    const float* W_b   = (const float*)d_in[7];
    const float* b_b   = (const float*)d_in[8];
    const float* W_c   = (const float*)d_in[9];
    const float* b_c   = (const float*)d_in[10];
    const float* W_cls = (const float*)d_in[11];
    const float* b_cls = (const float*)d_in[12];
    float* out = (float*)d_out;

    void *px, *pP, *pQ, *pg, *pAp, *pBp, *pd2;
    cudaGetSymbolAddress(&px, d_x);
    cudaGetSymbolAddress(&pP, d_P);
    cudaGetSymbolAddress(&pQ, d_Q);
    cudaGetSymbolAddress(&pg, d_g);
    cudaGetSymbolAddress(&pAp, d_Ap);
    cudaGetSymbolAddress(&pBp, d_Bp);
    cudaGetSymbolAddress(&pd2, d_d2);
    float* x  = (float*)px;
    float* P  = (float*)pP;
    float* Q  = (float*)pQ;
    float* g  = (float*)pg;
    float* Ap = (float*)pAp;
    float* Bp = (float*)pBp;
    float* d2 = (float*)pd2;

    // 1. x = relu(h @ W_fc + b_fc)  — fp32 FFMA exact (kNN-critical)
    gemm_f32_relu<<<dim3(HD / FBN, MROWS / FBM), 256>>>(h, W_fc, b_fc, x, MROWS, DIM, HD);
    // 2. squared norms
    sqnorm_kernel<<<MROWS, 128>>>();
    // 3. per-bag Gram -> approx d2 — bf16-3x (upper blocks + mirror)
    gemm_bf<2, 1><<<dim3(NI / XBN, NI / XBM, NB), 256>>>(x, x, d2, NI, HD, NI);
    // 4a. approx top-KC candidates
    topk_kernel<<<MROWS / 4, 128>>>();
    // 4b. exact fp32 re-rank -> top-KN
    rerank_kernel<<<MROWS, KC * 32>>>();
    // 5/6. P = x@Wg_top, Q = x@Wg_bot — bf16-3x
    gemm_bf<0, 0><<<dim3(HD / XBN, MROWS / XBM), 256>>>(x, W_g, P, MROWS, HD, HD);
    gemm_bf<0, 0><<<dim3(HD / XBN, MROWS / XBM), 256>>>(x, W_g + (size_t)HD * HD, Q, MROWS, HD, HD);
    // 7. edgeconv gather + max (b_g added here)
    edgeconv_kernel<<<MROWS, 128>>>(b_g);
    // 8/9. attention pre-projections — bf16-3x (biases added in gate)
    gemm_bf<0, 0><<<dim3(DA / XBN, MROWS / XBM), 256>>>(g, W_a, Ap, MROWS, HD, DA);
    gemm_bf<0, 0><<<dim3(DA / XBN, MROWS / XBM), 256>>>(g, W_b, Bp, MROWS, HD, DA);
    // 10. gated attention score -> A_raw
    gate_kernel<<<MROWS, 128>>>(b_a, b_b, W_c, b_c, out);
    // 11. softmax stats + zero M
    attn_stats_kernel<<<NB, 512>>>();
    // 12. chunked weighted pooling
    pool_acc_kernel<<<dim3(NB, 16), 256>>>();
    // 13. classifier head + Y_prob
    head_kernel<<<NB, 128>>>(W_cls, b_cls, out);
}